// round 11
// baseline (speedup 1.0000x reference)
#include <cuda_runtime.h>
#include <cuda_fp16.h>
#include <math.h>
#include <stdint.h>

#define N_POI 50000
#define DIM 128
#define E_EDGES 400000
#define GCN_NUM 3
#define BATCH 64
#define LSEQ 100
#define NTOK (BATCH*LSEQ)
#define DIRE (2*E_EDGES)

// ---------------- device scratch ----------------
__device__ __align__(16) int    g_cnt[N_POI];
__device__ __align__(16) int    g_rowptr[N_POI+1];
__device__ __align__(16) int    g_rowcur[N_POI];
__device__ __align__(16) float  g_dis[N_POI];
__device__ __align__(16) int    g_colidx[DIRE];
__device__ __align__(16) float  g_wcsr[DIRE];
__device__ __align__(16) float  g_bufA[N_POI*DIM];
__device__ __align__(16) __half g_aggH[N_POI*DIM];
__device__ __align__(16) __half g_encH[N_POI*DIM];
__device__ __align__(16) float  g_qkv[NTOK*3*DIM];
__device__ __align__(16) float  g_o[NTOK*DIM];

// packed fp32x2 FMA (exact fp32 numerics, 2x FMA-pipe rate)
__device__ __forceinline__ void ffma2(unsigned long long &d,
                                      unsigned long long a,
                                      unsigned long long b){
    asm("fma.rn.f32x2 %0, %1, %2, %0;" : "+l"(d) : "l"(a), "l"(b));
}
__device__ __forceinline__ float pair_sum(unsigned long long v){
    float2 f;
    asm("mov.b64 {%0, %1}, %2;" : "=f"(f.x), "=f"(f.y) : "l"(v));
    return f.x + f.y;
}

// ---------------- #1: hist + fp16 convert of embeds ----------------
__global__ void k_hist_cvt(const int* __restrict__ e0, const int* __restrict__ e1,
                           int* cnt, const float4* __restrict__ emb4,
                           __half2* __restrict__ encH2){
    int i = blockIdx.x*256 + threadIdx.x;
    if (i < E_EDGES){
        atomicAdd(&cnt[e0[i]], 1);
        atomicAdd(&cnt[e1[i]], 1);
    }
    for (int j = i; j < N_POI*32; j += gridDim.x*256){
        float4 v = emb4[j];
        encH2[j*2]     = __floats2half2_rn(v.x, v.y);
        encH2[j*2 + 1] = __floats2half2_rn(v.z, v.w);
    }
}
// ---------------- #2: scan ----------------
__global__ void k_scan(const int* __restrict__ cnt, int* __restrict__ rowptr,
                       int* __restrict__ rowcur, float* __restrict__ dis){
    __shared__ int sh[1024];
    int t = threadIdx.x;
    const int CH = (N_POI + 1023)/1024;
    int base = t*CH;
    int s = 0;
    for (int i = 0; i < CH; i++){
        int idx = base + i;
        if (idx < N_POI) s += cnt[idx];
    }
    sh[t] = s;
    __syncthreads();
    for (int o = 1; o < 1024; o <<= 1){
        int v = (t >= o) ? sh[t-o] : 0;
        __syncthreads();
        sh[t] += v;
        __syncthreads();
    }
    int off = (t == 0) ? 0 : sh[t-1];
    for (int i = 0; i < CH; i++){
        int idx = base + i;
        if (idx < N_POI){
            int c = cnt[idx];
            rowptr[idx] = off;
            rowcur[idx] = off;
            dis[idx] = rsqrtf((float)(c + 1));
            off += c;
        }
    }
    if (t == 1023) rowptr[N_POI] = sh[1023];
}
// ---------------- #3: scatter ----------------
__global__ void k_scatter(const int* __restrict__ e0, const int* __restrict__ e1,
                          const float* __restrict__ dv, const float* __restrict__ dis,
                          int* rowcur, int* __restrict__ colidx, float* __restrict__ wcsr){
    int e = blockIdx.x*256 + threadIdx.x;
    if (e >= E_EDGES) return;
    int a = e0[e], b = e1[e];
    float d = dv[e];
    float wv = expf(-d*d) * dis[a] * dis[b];
    int p = atomicAdd(&rowcur[a], 1);
    colidx[p] = b; wcsr[p] = wv;
    p = atomicAdd(&rowcur[b], 1);
    colidx[p] = a; wcsr[p] = wv;
}

// ---------------- #4: SpMM fp16 gather -> fp16 agg (proven R10 version) ----------------
__global__ void k_spmm2(const uint2* __restrict__ encH2, const int* __restrict__ rowptr,
                        const int* __restrict__ cols, const float* __restrict__ ws,
                        const float* __restrict__ dis, uint2* __restrict__ aggH2){
    int row = blockIdx.x*8 + (threadIdx.x >> 5);
    int lane = threadIdx.x & 31;
    if (row >= N_POI) return;
    float ds = dis[row];
    float sl = ds*ds;

    uint2 xs = encH2[row*32 + lane];
    float2 xa = __half22float2(*(const __half2*)&xs.x);
    float2 xb = __half22float2(*(const __half2*)&xs.y);
    float4 acc = make_float4(sl*xa.x, sl*xa.y, sl*xb.x, sl*xb.y);

    int s = __ldg(&rowptr[row]), e = __ldg(&rowptr[row+1]);
    int i = s;
    for (; i + 4 <= e; i += 4){
        int c0 = __ldg(&cols[i]),   c1 = __ldg(&cols[i+1]);
        int c2 = __ldg(&cols[i+2]), c3 = __ldg(&cols[i+3]);
        float w0 = __ldg(&ws[i]),   w1 = __ldg(&ws[i+1]);
        float w2 = __ldg(&ws[i+2]), w3 = __ldg(&ws[i+3]);
        uint2 u0 = encH2[c0*32 + lane];
        uint2 u1 = encH2[c1*32 + lane];
        uint2 u2 = encH2[c2*32 + lane];
        uint2 u3 = encH2[c3*32 + lane];
        float2 a0 = __half22float2(*(const __half2*)&u0.x), b0 = __half22float2(*(const __half2*)&u0.y);
        float2 a1 = __half22float2(*(const __half2*)&u1.x), b1 = __half22float2(*(const __half2*)&u1.y);
        float2 a2 = __half22float2(*(const __half2*)&u2.x), b2 = __half22float2(*(const __half2*)&u2.y);
        float2 a3 = __half22float2(*(const __half2*)&u3.x), b3 = __half22float2(*(const __half2*)&u3.y);
        acc.x = fmaf(w3,a3.x, fmaf(w2,a2.x, fmaf(w1,a1.x, fmaf(w0,a0.x, acc.x))));
        acc.y = fmaf(w3,a3.y, fmaf(w2,a2.y, fmaf(w1,a1.y, fmaf(w0,a0.y, acc.y))));
        acc.z = fmaf(w3,b3.x, fmaf(w2,b2.x, fmaf(w1,b1.x, fmaf(w0,b0.x, acc.z))));
        acc.w = fmaf(w3,b3.y, fmaf(w2,b2.y, fmaf(w1,b1.y, fmaf(w0,b0.y, acc.w))));
    }
    for (; i < e; i++){
        int c = __ldg(&cols[i]);
        float wv = __ldg(&ws[i]);
        uint2 u = encH2[c*32 + lane];
        float2 a = __half22float2(*(const __half2*)&u.x);
        float2 b = __half22float2(*(const __half2*)&u.y);
        acc.x = fmaf(wv, a.x, acc.x);
        acc.y = fmaf(wv, a.y, acc.y);
        acc.z = fmaf(wv, b.x, acc.z);
        acc.w = fmaf(wv, b.y, acc.w);
    }
    uint2 o;
    *(__half2*)&o.x = __floats2half2_rn(acc.x, acc.y);
    *(__half2*)&o.y = __floats2half2_rn(acc.z, acc.w);
    aggH2[row*32 + lane] = o;
}

// ---------------- #5: FFMA2 GEMM + lrelu + row L2-norm ----------------
// 512 threads, 8x4 microtile. Warp = one 8-row group spanning all 128 cols.
__global__ void __launch_bounds__(512, 1)
k_gemm_x2(const uint2* __restrict__ aggH2, const float4* __restrict__ W4,
          const float* __restrict__ bias, float4* __restrict__ Y4,
          uint2* __restrict__ YhU2, int M, int write_f32){
    extern __shared__ float4 sg4[];
    float4* Xs = sg4;          // [128][32], plain (broadcast reads)
    float4* Ws = sg4 + 4096;   // [128][32], col swizzle k4 ^ ((n>>2)&7)
    int tid = threadIdx.x;
    int row0 = blockIdx.x * 128;

    for (int i = tid; i < 4096; i += 512){
        int r = i >> 5, k4 = i & 31;
        int grow = row0 + r;
        float4 xv = make_float4(0.f,0.f,0.f,0.f);
        if (grow < M){
            uint2 av = aggH2[grow*32 + k4];
            float2 lo = __half22float2(*(const __half2*)&av.x);
            float2 hi = __half22float2(*(const __half2*)&av.y);
            xv = make_float4(lo.x, lo.y, hi.x, hi.y);
        }
        Xs[i] = xv;
        Ws[r*32 + (k4 ^ ((r >> 2) & 7))] = W4[i];
    }
    __syncthreads();

    int ty = tid >> 5, tx = tid & 31;   // rows ty*8+r, cols tx*4+c
    unsigned long long acc[8][4];
    #pragma unroll
    for (int r = 0; r < 8; r++)
        #pragma unroll
        for (int c = 0; c < 4; c++) acc[r][c] = 0ull;

    const ulonglong2* Xp = (const ulonglong2*)(Xs + (ty*8)*32);
    const ulonglong2* Wp = (const ulonglong2*)Ws;
    int swz = tx & 7;
    #pragma unroll 2
    for (int k4 = 0; k4 < 32; k4++){
        ulonglong2 xv[8], wv[4];
        #pragma unroll
        for (int r = 0; r < 8; r++) xv[r] = Xp[r*32 + k4];   // broadcast
        int kk = k4 ^ swz;
        #pragma unroll
        for (int c = 0; c < 4; c++) wv[c] = Wp[(tx*4 + c)*32 + kk];
        #pragma unroll
        for (int r = 0; r < 8; r++)
            #pragma unroll
            for (int c = 0; c < 4; c++){
                ffma2(acc[r][c], xv[r].x, wv[c].x);
                ffma2(acc[r][c], xv[r].y, wv[c].y);
            }
    }

    float bj[4];
    #pragma unroll
    for (int c = 0; c < 4; c++) bj[c] = __ldg(&bias[tx*4 + c]);

    #pragma unroll
    for (int r = 0; r < 8; r++){
        float v[4];
        float ss = 0.f;
        #pragma unroll
        for (int c = 0; c < 4; c++){
            float t = pair_sum(acc[r][c]) + bj[c];
            t = (t >= 0.f) ? t : 0.01f*t;
            v[c] = t;
            ss = fmaf(t, t, ss);
        }
        #pragma unroll
        for (int o = 16; o > 0; o >>= 1) ss += __shfl_xor_sync(0xffffffffu, ss, o);
        float inv = 1.0f / fmaxf(sqrtf(ss), 1e-12f);
        int grow = row0 + ty*8 + r;
        if (grow < M){
            float y0 = v[0]*inv, y1 = v[1]*inv, y2 = v[2]*inv, y3 = v[3]*inv;
            if (write_f32) Y4[grow*32 + tx] = make_float4(y0, y1, y2, y3);
            uint2 oh;
            *(__half2*)&oh.x = __floats2half2_rn(y0, y1);
            *(__half2*)&oh.y = __floats2half2_rn(y2, y3);
            YhU2[grow*32 + tx] = oh;
        }
    }
}

// ---------------- QKV: FFMA2 GEMM, gathered rows ----------------
__global__ void __launch_bounds__(512, 1)
k_qkv_x2(const float4* __restrict__ enc4, const int* __restrict__ xidx,
         const float* __restrict__ inw, const float* __restrict__ inb,
         float4* __restrict__ qkv4){
    extern __shared__ float4 sg4[];
    float4* Xs = sg4;
    float4* Ws = sg4 + 4096;
    int tid = threadIdx.x;
    int row0 = blockIdx.x * 128;
    int nb = blockIdx.y;
    const float4* W4 = (const float4*)(inw + nb*DIM*DIM);
    for (int i = tid; i < 4096; i += 512){
        int r = i >> 5, k4 = i & 31;
        int src = __ldg(&xidx[row0 + r]);
        Xs[i] = enc4[src*32 + k4];
        Ws[r*32 + (k4 ^ ((r >> 2) & 7))] = W4[i];
    }
    __syncthreads();

    int ty = tid >> 5, tx = tid & 31;
    unsigned long long acc[8][4];
    #pragma unroll
    for (int r = 0; r < 8; r++)
        #pragma unroll
        for (int c = 0; c < 4; c++) acc[r][c] = 0ull;

    const ulonglong2* Xp = (const ulonglong2*)(Xs + (ty*8)*32);
    const ulonglong2* Wp = (const ulonglong2*)Ws;
    int swz = tx & 7;
    #pragma unroll 2
    for (int k4 = 0; k4 < 32; k4++){
        ulonglong2 xv[8], wv[4];
        #pragma unroll
        for (int r = 0; r < 8; r++) xv[r] = Xp[r*32 + k4];
        int kk = k4 ^ swz;
        #pragma unroll
        for (int c = 0; c < 4; c++) wv[c] = Wp[(tx*4 + c)*32 + kk];
        #pragma unroll
        for (int r = 0; r < 8; r++)
            #pragma unroll
            for (int c = 0; c < 4; c++){
                ffma2(acc[r][c], xv[r].x, wv[c].x);
                ffma2(acc[r][c], xv[r].y, wv[c].y);
            }
    }

    float bj[4];
    #pragma unroll
    for (int c = 0; c < 4; c++) bj[c] = __ldg(&inb[nb*DIM + tx*4 + c]);
    #pragma unroll
    for (int r = 0; r < 8; r++){
        int t = row0 + ty*8 + r;
        qkv4[t*96 + nb*32 + tx] = make_float4(
            pair_sum(acc[r][0]) + bj[0], pair_sum(acc[r][1]) + bj[1],
            pair_sum(acc[r][2]) + bj[2], pair_sum(acc[r][3]) + bj[3]);
    }
}

// ---------------- attention: conflict-free, one block per (b, h) ----------------
__global__ void k_attn(const float* __restrict__ qkv, float* __restrict__ o){
    extern __shared__ float sha[];
    float* sq  = sha;
    float* skT = sha + LSEQ*16;
    float* sv  = sha + 2*LSEQ*16;
    float* sp  = sha + 3*LSEQ*16;
    int b = blockIdx.x, h = blockIdx.y;
    int tid = threadIdx.x;
    for (int idx = tid; idx < LSEQ*16; idx += 128){
        int t = idx >> 4, d = idx & 15;
        int base = (b*LSEQ + t)*(3*DIM) + h*16 + d;
        sq[idx] = qkv[base];
        sv[idx] = qkv[base + 2*DIM];
    }
    for (int idx = tid; idx < LSEQ*16; idx += 128){
        int d = idx / LSEQ, t = idx - d*LSEQ;
        skT[idx] = qkv[(b*LSEQ + t)*(3*DIM) + DIM + h*16 + d];
    }
    __syncthreads();

    int lane = tid & 31, warp = tid >> 5;
    for (int qi = warp; qi < LSEQ; qi += 4){
        float q[16];
        #pragma unroll
        for (int d = 0; d < 16; d++) q[d] = sq[qi*16 + d];
        float v[4];
        float m = -1e30f;
        #pragma unroll
        for (int g = 0; g < 4; g++){
            int j = lane + g*32;
            float s = -1e30f;
            if (j < LSEQ){
                s = 0.f;
                #pragma unroll
                for (int d = 0; d < 16; d++) s = fmaf(q[d], skT[d*LSEQ + j], s);
                s *= 0.25f;
            }
            v[g] = s;
            m = fmaxf(m, s);
        }
        #pragma unroll
        for (int t = 16; t > 0; t >>= 1) m = fmaxf(m, __shfl_xor_sync(0xffffffffu, m, t));
        float ssum = 0.f;
        #pragma unroll
        for (int g = 0; g < 4; g++){
            int j = lane + g*32;
            float p = (j < LSEQ) ? __expf(v[g] - m) : 0.f;
            v[g] = p;
            ssum += p;
        }
        #pragma unroll
        for (int t = 16; t > 0; t >>= 1) ssum += __shfl_xor_sync(0xffffffffu, ssum, t);
        float inv = 1.0f / ssum;
        #pragma unroll
        for (int g = 0; g < 4; g++){
            int j = lane + g*32;
            if (j < LSEQ) sp[qi*LSEQ + j] = v[g]*inv;
        }
    }
    __syncthreads();

    const float4* sv4 = (const float4*)sv;
    for (int u = tid; u < LSEQ*4; u += 128){
        int qi = u >> 2, dg = u & 3;
        float4 acc = make_float4(0.f,0.f,0.f,0.f);
        const float* pp = sp + qi*LSEQ;
        #pragma unroll 4
        for (int j = 0; j < LSEQ; j++){
            float p = pp[j];
            float4 vv = sv4[j*4 + dg];
            acc.x = fmaf(p, vv.x, acc.x);
            acc.y = fmaf(p, vv.y, acc.y);
            acc.z = fmaf(p, vv.z, acc.z);
            acc.w = fmaf(p, vv.w, acc.w);
        }
        *(float4*)&o[(b*LSEQ + qi)*DIM + h*16 + dg*4] = acc;
    }
}

// ---------------- mean over L + out-projection + target gather ----------------
__global__ void k_tail(const float* __restrict__ o, const float* __restrict__ ow,
                       const float* __restrict__ ob, const float* __restrict__ enc,
                       const int* __restrict__ pidx, float* __restrict__ out){
    __shared__ float sx[DIM];
    int b = blockIdx.x, j = threadIdx.x;
    float s = 0.0f;
    for (int i = 0; i < LSEQ; i++) s += o[(b*LSEQ + i)*DIM + j];
    sx[j] = s * (1.0f/LSEQ);
    __syncthreads();
    float acc = ob[j];
    #pragma unroll 4
    for (int k = 0; k < DIM; k++) acc += sx[k]*ow[j*DIM + k];
    out[b*DIM + j] = acc;
    out[BATCH*DIM + b*DIM + j] = enc[pidx[b]*DIM + j];
}

// ---------------- host launch ----------------
extern "C" void kernel_launch(void* const* d_in, const int* in_sizes, int n_in,
                              void* d_out, int out_size){
    const float* embeds = (const float*)d_in[0];
    const float* gcnW   = (const float*)d_in[1];
    const float* gcnb   = (const float*)d_in[2];
    const float* inw    = (const float*)d_in[3];
    const float* inb    = (const float*)d_in[4];
    const float* ow     = (const float*)d_in[5];
    const float* ob     = (const float*)d_in[6];
    const float* dv     = (const float*)d_in[7];
    const int*   edges  = (const int*)d_in[8];
    const int*   xidx   = (const int*)d_in[9];
    const int*   pidx   = (const int*)d_in[10];
    const int* e0 = edges;
    const int* e1 = edges + E_EDGES;
    float* out = (float*)d_out;

    int *cnt, *rowptr, *rowcur, *colidx;
    float *dis, *wcsr, *bA, *qkv, *obuf;
    __half *encH, *aggH;
    cudaGetSymbolAddress((void**)&cnt,    g_cnt);
    cudaGetSymbolAddress((void**)&rowptr, g_rowptr);
    cudaGetSymbolAddress((void**)&rowcur, g_rowcur);
    cudaGetSymbolAddress((void**)&dis,    g_dis);
    cudaGetSymbolAddress((void**)&colidx, g_colidx);
    cudaGetSymbolAddress((void**)&wcsr,   g_wcsr);
    cudaGetSymbolAddress((void**)&bA,     g_bufA);
    cudaGetSymbolAddress((void**)&aggH,   g_aggH);
    cudaGetSymbolAddress((void**)&encH,   g_encH);
    cudaGetSymbolAddress((void**)&qkv,    g_qkv);
    cudaGetSymbolAddress((void**)&obuf,   g_o);

    const int smem_gemm = 2*4096*(int)sizeof(float4);   // 131072
    const int smem_attn = (3*LSEQ*16 + LSEQ*LSEQ)*(int)sizeof(float);
    cudaFuncSetAttribute(k_gemm_x2, cudaFuncAttributeMaxDynamicSharedMemorySize, smem_gemm);
    cudaFuncSetAttribute(k_qkv_x2,  cudaFuncAttributeMaxDynamicSharedMemorySize, smem_gemm);
    cudaFuncSetAttribute(k_attn,    cudaFuncAttributeMaxDynamicSharedMemorySize, smem_attn);

    // launch order: hist_cvt(1) scan(2) scatter(3) spmm(4 <- ncu slot) gemm(5) ...
    cudaMemsetAsync(cnt, 0, N_POI*sizeof(int));
    k_hist_cvt<<<(N_POI*32+255)/256, 256>>>(e0, e1, cnt, (const float4*)embeds,
                                            (__half2*)encH);
    k_scan<<<1, 1024>>>(cnt, rowptr, rowcur, dis);
    k_scatter<<<(E_EDGES+255)/256, 256>>>(e0, e1, dv, dis, rowcur, colidx, wcsr);

    // 3 GCN layers
    for (int i = 0; i < GCN_NUM; i++){
        k_spmm2<<<(N_POI+7)/8, 256>>>((const uint2*)encH, rowptr, colidx, wcsr, dis,
                                       (uint2*)aggH);
        k_gemm_x2<<<(N_POI+127)/128, 512, smem_gemm>>>(
            (const uint2*)aggH, (const float4*)(gcnW + i*DIM*DIM), gcnb + i*DIM,
            (float4*)bA, (uint2*)encH, N_POI, (i == GCN_NUM-1) ? 1 : 0);
    }
    const float* encF = bA;

    // attention
    k_qkv_x2<<<dim3(NTOK/128, 3), 512, smem_gemm>>>((const float4*)encF, xidx, inw, inb,
                                                    (float4*)qkv);
    k_attn<<<dim3(BATCH, 8), 128, smem_attn>>>(qkv, obuf);
    k_tail<<<BATCH, 128>>>(obuf, ow, ob, encF, pidx, out);
}

// round 12
// speedup vs baseline: 1.3035x; 1.3035x over previous
#include <cuda_runtime.h>
#include <cuda_fp16.h>
#include <math.h>
#include <stdint.h>

#define N_POI 50000
#define DIM 128
#define E_EDGES 400000
#define GCN_NUM 3
#define BATCH 64
#define LSEQ 100
#define NTOK (BATCH*LSEQ)
#define DIRE (2*E_EDGES)

// ---------------- device scratch ----------------
__device__ __align__(16) int    g_cnt[N_POI];
__device__ __align__(16) int    g_rowptr[N_POI+1];
__device__ __align__(16) int    g_rowcur[N_POI];
__device__ __align__(16) float  g_dis[N_POI];
__device__ __align__(16) int    g_colidx[DIRE];
__device__ __align__(16) float  g_wcsr[DIRE];
__device__ __align__(16) float  g_bufA[N_POI*DIM];
__device__ __align__(16) __half g_tmpH[N_POI*DIM];   // GEMM output (XW), fp16
__device__ __align__(16) __half g_encH[N_POI*DIM];   // enc, fp16
__device__ __align__(16) __half g_WH[GCN_NUM*DIM*DIM];
__device__ __align__(16) float  g_qkv[NTOK*3*DIM];
__device__ __align__(16) float  g_o[NTOK*DIM];

// fp16 HMMA m16n8k16, fp32 accumulate
__device__ __forceinline__ void mma_f16(float* d, const uint32_t* a, const uint32_t* b){
    asm volatile("mma.sync.aligned.m16n8k16.row.col.f32.f16.f16.f32 "
        "{%0,%1,%2,%3}, {%4,%5,%6,%7}, {%8,%9}, {%0,%1,%2,%3};"
        : "+f"(d[0]), "+f"(d[1]), "+f"(d[2]), "+f"(d[3])
        : "r"(a[0]), "r"(a[1]), "r"(a[2]), "r"(a[3]), "r"(b[0]), "r"(b[1]));
}

// ---------------- #1: fp16 convert of embeds + gcn weights ----------------
__global__ void k_cvt(const float4* __restrict__ emb4, const float4* __restrict__ w4,
                      __half2* __restrict__ encH2, __half2* __restrict__ WH2){
    const int NE4 = N_POI*32;
    const int NW4 = GCN_NUM*DIM*32;
    for (int j = blockIdx.x*256 + threadIdx.x; j < NE4 + NW4; j += gridDim.x*256){
        if (j < NE4){
            float4 v = emb4[j];
            encH2[j*2]     = __floats2half2_rn(v.x, v.y);
            encH2[j*2 + 1] = __floats2half2_rn(v.z, v.w);
        } else {
            int k = j - NE4;
            float4 v = w4[k];
            WH2[k*2]     = __floats2half2_rn(v.x, v.y);
            WH2[k*2 + 1] = __floats2half2_rn(v.z, v.w);
        }
    }
}
// ---------------- #2: histogram ----------------
__global__ void k_hist(const int* __restrict__ e0, const int* __restrict__ e1, int* cnt){
    int e = blockIdx.x*256 + threadIdx.x;
    if (e < E_EDGES){
        atomicAdd(&cnt[e0[e]], 1);
        atomicAdd(&cnt[e1[e]], 1);
    }
}
// ---------------- #3: scan ----------------
__global__ void k_scan(const int* __restrict__ cnt, int* __restrict__ rowptr,
                       int* __restrict__ rowcur, float* __restrict__ dis){
    __shared__ int sh[1024];
    int t = threadIdx.x;
    const int CH = (N_POI + 1023)/1024;
    int base = t*CH;
    int s = 0;
    for (int i = 0; i < CH; i++){
        int idx = base + i;
        if (idx < N_POI) s += cnt[idx];
    }
    sh[t] = s;
    __syncthreads();
    for (int o = 1; o < 1024; o <<= 1){
        int v = (t >= o) ? sh[t-o] : 0;
        __syncthreads();
        sh[t] += v;
        __syncthreads();
    }
    int off = (t == 0) ? 0 : sh[t-1];
    for (int i = 0; i < CH; i++){
        int idx = base + i;
        if (idx < N_POI){
            int c = cnt[idx];
            rowptr[idx] = off;
            rowcur[idx] = off;
            dis[idx] = rsqrtf((float)(c + 1));
            off += c;
        }
    }
    if (t == 1023) rowptr[N_POI] = sh[1023];
}
// ---------------- #5: scatter ----------------
__global__ void k_scatter(const int* __restrict__ e0, const int* __restrict__ e1,
                          const float* __restrict__ dv, const float* __restrict__ dis,
                          int* rowcur, int* __restrict__ colidx, float* __restrict__ wcsr){
    int e = blockIdx.x*256 + threadIdx.x;
    if (e >= E_EDGES) return;
    int a = e0[e], b = e1[e];
    float d = dv[e];
    float wv = expf(-d*d) * dis[a] * dis[b];
    int p = atomicAdd(&rowcur[a], 1);
    colidx[p] = b; wcsr[p] = wv;
    p = atomicAdd(&rowcur[b], 1);
    colidx[p] = a; wcsr[p] = wv;
}

// ---------------- #4 (ncu slot): pure fp16 HMMA GEMM  tmp = X @ W^T ----------------
#define PH 136
__global__ void __launch_bounds__(256, 2)
k_gemm_p(const uint2* __restrict__ Xh2, const uint2* __restrict__ WH2,
         uint32_t* __restrict__ tmpH, int M){
    extern __shared__ __half shh[];
    __half* As = shh;            // [128][PH]
    __half* Bs = shh + 128*PH;
    int tid = threadIdx.x;
    int row0 = blockIdx.x * 128;

    for (int i = tid; i < 128*32; i += 256){
        int r = i >> 5, c8 = i & 31;
        int grow = row0 + r;
        uint2 av = (grow < M) ? Xh2[grow*32 + c8] : make_uint2(0u, 0u);
        *(uint2*)&As[r*PH + c8*4] = av;
        *(uint2*)&Bs[r*PH + c8*4] = WH2[i];
    }
    __syncthreads();

    int wid = tid >> 5, lane = tid & 31;
    int wm = wid & 1, wn = wid >> 1;
    int m_base = wm*64, n_base = wn*32;
    int qr = lane >> 2, qc = lane & 3;

    float acc[4][4][4];
    #pragma unroll
    for (int mi = 0; mi < 4; mi++)
        #pragma unroll
        for (int ni = 0; ni < 4; ni++)
            #pragma unroll
            for (int j = 0; j < 4; j++) acc[mi][ni][j] = 0.f;

    #pragma unroll
    for (int k0 = 0; k0 < 128; k0 += 16){
        uint32_t a[4][4];
        #pragma unroll
        for (int mi = 0; mi < 4; mi++){
            const __half* ap = As + (m_base + mi*16 + qr)*PH + k0 + 2*qc;
            a[mi][0] = *(const uint32_t*)ap;
            a[mi][1] = *(const uint32_t*)(ap + 8*PH);
            a[mi][2] = *(const uint32_t*)(ap + 8);
            a[mi][3] = *(const uint32_t*)(ap + 8*PH + 8);
        }
        uint32_t b[4][2];
        #pragma unroll
        for (int ni = 0; ni < 4; ni++){
            const __half* bp = Bs + (n_base + ni*8 + qr)*PH + k0 + 2*qc;
            b[ni][0] = *(const uint32_t*)bp;
            b[ni][1] = *(const uint32_t*)(bp + 8);
        }
        #pragma unroll
        for (int mi = 0; mi < 4; mi++)
            #pragma unroll
            for (int ni = 0; ni < 4; ni++)
                mma_f16(acc[mi][ni], a[mi], b[ni]);
    }

    #pragma unroll
    for (int mi = 0; mi < 4; mi++){
        int r0 = row0 + m_base + mi*16 + qr;
        int r1 = r0 + 8;
        #pragma unroll
        for (int ni = 0; ni < 4; ni++){
            float* d = acc[mi][ni];
            int col = n_base + ni*8 + qc*2;
            if (r0 < M){
                __half2 h = __floats2half2_rn(d[0], d[1]);
                tmpH[r0*64 + (col >> 1)] = *(uint32_t*)&h;
            }
            if (r1 < M){
                __half2 h = __floats2half2_rn(d[2], d[3]);
                tmpH[r1*64 + (col >> 1)] = *(uint32_t*)&h;
            }
        }
    }
}

// ---------------- #6: SpMM on tmp + fused bias/lrelu/row-norm epilogue ----------------
__global__ void k_spmm_f(const uint2* __restrict__ tmpH2, const int* __restrict__ rowptr,
                         const int* __restrict__ cols, const float* __restrict__ ws,
                         const float* __restrict__ dis, const float4* __restrict__ bias4,
                         uint2* __restrict__ encH2, float4* __restrict__ outF4,
                         int writeF){
    int row = blockIdx.x*8 + (threadIdx.x >> 5);
    int lane = threadIdx.x & 31;
    if (row >= N_POI) return;
    float ds = dis[row];
    float sl = ds*ds;

    uint2 xs = tmpH2[row*32 + lane];
    float2 xa = __half22float2(*(const __half2*)&xs.x);
    float2 xb = __half22float2(*(const __half2*)&xs.y);
    float4 acc = make_float4(sl*xa.x, sl*xa.y, sl*xb.x, sl*xb.y);

    int s = __ldg(&rowptr[row]), e = __ldg(&rowptr[row+1]);
    int i = s;
    for (; i + 4 <= e; i += 4){
        int c0 = __ldg(&cols[i]),   c1 = __ldg(&cols[i+1]);
        int c2 = __ldg(&cols[i+2]), c3 = __ldg(&cols[i+3]);
        float w0 = __ldg(&ws[i]),   w1 = __ldg(&ws[i+1]);
        float w2 = __ldg(&ws[i+2]), w3 = __ldg(&ws[i+3]);
        uint2 u0 = tmpH2[c0*32 + lane];
        uint2 u1 = tmpH2[c1*32 + lane];
        uint2 u2 = tmpH2[c2*32 + lane];
        uint2 u3 = tmpH2[c3*32 + lane];
        float2 a0 = __half22float2(*(const __half2*)&u0.x), b0 = __half22float2(*(const __half2*)&u0.y);
        float2 a1 = __half22float2(*(const __half2*)&u1.x), b1 = __half22float2(*(const __half2*)&u1.y);
        float2 a2 = __half22float2(*(const __half2*)&u2.x), b2 = __half22float2(*(const __half2*)&u2.y);
        float2 a3 = __half22float2(*(const __half2*)&u3.x), b3 = __half22float2(*(const __half2*)&u3.y);
        acc.x = fmaf(w3,a3.x, fmaf(w2,a2.x, fmaf(w1,a1.x, fmaf(w0,a0.x, acc.x))));
        acc.y = fmaf(w3,a3.y, fmaf(w2,a2.y, fmaf(w1,a1.y, fmaf(w0,a0.y, acc.y))));
        acc.z = fmaf(w3,b3.x, fmaf(w2,b2.x, fmaf(w1,b1.x, fmaf(w0,b0.x, acc.z))));
        acc.w = fmaf(w3,b3.y, fmaf(w2,b2.y, fmaf(w1,b1.y, fmaf(w0,b0.y, acc.w))));
    }
    for (; i < e; i++){
        int c = __ldg(&cols[i]);
        float wv = __ldg(&ws[i]);
        uint2 u = tmpH2[c*32 + lane];
        float2 a = __half22float2(*(const __half2*)&u.x);
        float2 b = __half22float2(*(const __half2*)&u.y);
        acc.x = fmaf(wv, a.x, acc.x);
        acc.y = fmaf(wv, a.y, acc.y);
        acc.z = fmaf(wv, b.x, acc.z);
        acc.w = fmaf(wv, b.y, acc.w);
    }

    // epilogue: bias + lrelu + row L2-norm (warp owns the full row)
    float4 b = bias4[lane];
    float v0 = acc.x + b.x, v1 = acc.y + b.y, v2 = acc.z + b.z, v3 = acc.w + b.w;
    v0 = (v0 >= 0.f) ? v0 : 0.01f*v0;
    v1 = (v1 >= 0.f) ? v1 : 0.01f*v1;
    v2 = (v2 >= 0.f) ? v2 : 0.01f*v2;
    v3 = (v3 >= 0.f) ? v3 : 0.01f*v3;
    float ss = fmaf(v0,v0, fmaf(v1,v1, fmaf(v2,v2, v3*v3)));
    #pragma unroll
    for (int o = 16; o > 0; o >>= 1) ss += __shfl_xor_sync(0xffffffffu, ss, o);
    float inv = 1.0f / fmaxf(sqrtf(ss), 1e-12f);
    float y0 = v0*inv, y1 = v1*inv, y2 = v2*inv, y3 = v3*inv;
    uint2 oh;
    *(__half2*)&oh.x = __floats2half2_rn(y0, y1);
    *(__half2*)&oh.y = __floats2half2_rn(y2, y3);
    encH2[row*32 + lane] = oh;
    if (writeF) outF4[row*32 + lane] = make_float4(y0, y1, y2, y3);
}

// ---------------- QKV: scalar tiled GEMM (proven R10 version) ----------------
__global__ void __launch_bounds__(256, 1)
k_qkv2(const float4* __restrict__ enc4, const int* __restrict__ xidx,
       const float* __restrict__ inw, const float* __restrict__ inb,
       float4* __restrict__ qkv4){
    extern __shared__ float4 sh4[];
    float4* Xs = sh4;
    float4* Ws = sh4 + 4096;
    int tid = threadIdx.x;
    int row0 = blockIdx.x * 128;
    int nb = blockIdx.y;
    #pragma unroll
    for (int it = 0; it < 16; it++){
        int idx = tid + it*256;
        int m = idx >> 5, k4 = idx & 31;
        int src = __ldg(&xidx[row0 + m]);
        Xs[idx] = enc4[src*32 + k4];
    }
    const float4* W4 = (const float4*)(inw + nb*DIM*DIM);
    #pragma unroll
    for (int it = 0; it < 16; it++){
        int idx = tid + it*256;
        int n = idx >> 5, k4 = idx & 31;
        Ws[n*32 + (k4 ^ (n >> 3))] = W4[idx];
    }
    __syncthreads();

    int tx = tid & 15, ty = tid >> 4;
    float acc[8][8];
    #pragma unroll
    for (int r = 0; r < 8; r++)
        #pragma unroll
        for (int c = 0; c < 8; c++) acc[r][c] = 0.f;

    const float4* Xp = Xs + (ty*8)*32;
    const float4* Wp = Ws + (tx*8)*32;
    #pragma unroll 2
    for (int k4 = 0; k4 < 32; k4++){
        float4 xv[8], wv[8];
        #pragma unroll
        for (int r = 0; r < 8; r++) xv[r] = Xp[r*32 + k4];
        int ksw = k4 ^ tx;
        #pragma unroll
        for (int c = 0; c < 8; c++) wv[c] = Wp[c*32 + ksw];
        #pragma unroll
        for (int r = 0; r < 8; r++)
            #pragma unroll
            for (int c = 0; c < 8; c++){
                acc[r][c] = fmaf(xv[r].x, wv[c].x, acc[r][c]);
                acc[r][c] = fmaf(xv[r].y, wv[c].y, acc[r][c]);
                acc[r][c] = fmaf(xv[r].z, wv[c].z, acc[r][c]);
                acc[r][c] = fmaf(xv[r].w, wv[c].w, acc[r][c]);
            }
    }

    float bj[8];
    #pragma unroll
    for (int c = 0; c < 8; c++) bj[c] = __ldg(&inb[nb*DIM + tx*8 + c]);
    #pragma unroll
    for (int r = 0; r < 8; r++){
        int t = row0 + ty*8 + r;
        qkv4[t*96 + nb*32 + tx*2]     = make_float4(acc[r][0]+bj[0], acc[r][1]+bj[1], acc[r][2]+bj[2], acc[r][3]+bj[3]);
        qkv4[t*96 + nb*32 + tx*2 + 1] = make_float4(acc[r][4]+bj[4], acc[r][5]+bj[5], acc[r][6]+bj[6], acc[r][7]+bj[7]);
    }
}

// ---------------- attention: conflict-free, one block per (b, h) ----------------
__global__ void k_attn(const float* __restrict__ qkv, float* __restrict__ o){
    extern __shared__ float sha[];
    float* sq  = sha;
    float* skT = sha + LSEQ*16;
    float* sv  = sha + 2*LSEQ*16;
    float* sp  = sha + 3*LSEQ*16;
    int b = blockIdx.x, h = blockIdx.y;
    int tid = threadIdx.x;
    for (int idx = tid; idx < LSEQ*16; idx += 128){
        int t = idx >> 4, d = idx & 15;
        int base = (b*LSEQ + t)*(3*DIM) + h*16 + d;
        sq[idx] = qkv[base];
        sv[idx] = qkv[base + 2*DIM];
    }
    for (int idx = tid; idx < LSEQ*16; idx += 128){
        int d = idx / LSEQ, t = idx - d*LSEQ;
        skT[idx] = qkv[(b*LSEQ + t)*(3*DIM) + DIM + h*16 + d];
    }
    __syncthreads();

    int lane = tid & 31, warp = tid >> 5;
    for (int qi = warp; qi < LSEQ; qi += 4){
        float q[16];
        #pragma unroll
        for (int d = 0; d < 16; d++) q[d] = sq[qi*16 + d];
        float v[4];
        float m = -1e30f;
        #pragma unroll
        for (int g = 0; g < 4; g++){
            int j = lane + g*32;
            float s = -1e30f;
            if (j < LSEQ){
                s = 0.f;
                #pragma unroll
                for (int d = 0; d < 16; d++) s = fmaf(q[d], skT[d*LSEQ + j], s);
                s *= 0.25f;
            }
            v[g] = s;
            m = fmaxf(m, s);
        }
        #pragma unroll
        for (int t = 16; t > 0; t >>= 1) m = fmaxf(m, __shfl_xor_sync(0xffffffffu, m, t));
        float ssum = 0.f;
        #pragma unroll
        for (int g = 0; g < 4; g++){
            int j = lane + g*32;
            float p = (j < LSEQ) ? __expf(v[g] - m) : 0.f;
            v[g] = p;
            ssum += p;
        }
        #pragma unroll
        for (int t = 16; t > 0; t >>= 1) ssum += __shfl_xor_sync(0xffffffffu, ssum, t);
        float inv = 1.0f / ssum;
        #pragma unroll
        for (int g = 0; g < 4; g++){
            int j = lane + g*32;
            if (j < LSEQ) sp[qi*LSEQ + j] = v[g]*inv;
        }
    }
    __syncthreads();

    const float4* sv4 = (const float4*)sv;
    for (int u = tid; u < LSEQ*4; u += 128){
        int qi = u >> 2, dg = u & 3;
        float4 acc = make_float4(0.f,0.f,0.f,0.f);
        const float* pp = sp + qi*LSEQ;
        #pragma unroll 4
        for (int j = 0; j < LSEQ; j++){
            float p = pp[j];
            float4 vv = sv4[j*4 + dg];
            acc.x = fmaf(p, vv.x, acc.x);
            acc.y = fmaf(p, vv.y, acc.y);
            acc.z = fmaf(p, vv.z, acc.z);
            acc.w = fmaf(p, vv.w, acc.w);
        }
        *(float4*)&o[(b*LSEQ + qi)*DIM + h*16 + dg*4] = acc;
    }
}

// ---------------- mean over L + out-projection + target gather ----------------
__global__ void k_tail(const float* __restrict__ o, const float* __restrict__ ow,
                       const float* __restrict__ ob, const float* __restrict__ enc,
                       const int* __restrict__ pidx, float* __restrict__ out){
    __shared__ float sx[DIM];
    int b = blockIdx.x, j = threadIdx.x;
    float s = 0.0f;
    for (int i = 0; i < LSEQ; i++) s += o[(b*LSEQ + i)*DIM + j];
    sx[j] = s * (1.0f/LSEQ);
    __syncthreads();
    float acc = ob[j];
    #pragma unroll 4
    for (int k = 0; k < DIM; k++) acc += sx[k]*ow[j*DIM + k];
    out[b*DIM + j] = acc;
    out[BATCH*DIM + b*DIM + j] = enc[pidx[b]*DIM + j];
}

// ---------------- host launch ----------------
extern "C" void kernel_launch(void* const* d_in, const int* in_sizes, int n_in,
                              void* d_out, int out_size){
    const float* embeds = (const float*)d_in[0];
    const float* gcnW   = (const float*)d_in[1];
    const float* gcnb   = (const float*)d_in[2];
    const float* inw    = (const float*)d_in[3];
    const float* inb    = (const float*)d_in[4];
    const float* ow     = (const float*)d_in[5];
    const float* ob     = (const float*)d_in[6];
    const float* dv     = (const float*)d_in[7];
    const int*   edges  = (const int*)d_in[8];
    const int*   xidx   = (const int*)d_in[9];
    const int*   pidx   = (const int*)d_in[10];
    const int* e0 = edges;
    const int* e1 = edges + E_EDGES;
    float* out = (float*)d_out;

    int *cnt, *rowptr, *rowcur, *colidx;
    float *dis, *wcsr, *bA, *qkv, *obuf;
    __half *encH, *tmpH, *WH;
    cudaGetSymbolAddress((void**)&cnt,    g_cnt);
    cudaGetSymbolAddress((void**)&rowptr, g_rowptr);
    cudaGetSymbolAddress((void**)&rowcur, g_rowcur);
    cudaGetSymbolAddress((void**)&dis,    g_dis);
    cudaGetSymbolAddress((void**)&colidx, g_colidx);
    cudaGetSymbolAddress((void**)&wcsr,   g_wcsr);
    cudaGetSymbolAddress((void**)&bA,     g_bufA);
    cudaGetSymbolAddress((void**)&tmpH,   g_tmpH);
    cudaGetSymbolAddress((void**)&encH,   g_encH);
    cudaGetSymbolAddress((void**)&WH,     g_WH);
    cudaGetSymbolAddress((void**)&qkv,    g_qkv);
    cudaGetSymbolAddress((void**)&obuf,   g_o);

    const int smem_qkv  = 2*4096*(int)sizeof(float4);      // 131072
    const int smem_gemm = 2*128*PH*(int)sizeof(__half);    // 69632
    const int smem_attn = (3*LSEQ*16 + LSEQ*LSEQ)*(int)sizeof(float);
    cudaFuncSetAttribute(k_gemm_p, cudaFuncAttributeMaxDynamicSharedMemorySize, smem_gemm);
    cudaFuncSetAttribute(k_qkv2,   cudaFuncAttributeMaxDynamicSharedMemorySize, smem_qkv);
    cudaFuncSetAttribute(k_attn,   cudaFuncAttributeMaxDynamicSharedMemorySize, smem_attn);

    // order: cvt(1) hist(2) scan(3) gemm1(4 <- ncu slot) scatter(5) spmm1(6) ...
    cudaMemsetAsync(cnt, 0, N_POI*sizeof(int));
    k_cvt<<<6298, 256>>>((const float4*)embeds, (const float4*)gcnW,
                         (__half2*)encH, (__half2*)WH);
    k_hist<<<(E_EDGES+255)/256, 256>>>(e0, e1, cnt);
    k_scan<<<1, 1024>>>(cnt, rowptr, rowcur, dis);
    k_gemm_p<<<(N_POI+127)/128, 256, smem_gemm>>>(
        (const uint2*)encH, (const uint2*)WH, (uint32_t*)tmpH, N_POI);     // layer 1 GEMM
    k_scatter<<<(E_EDGES+255)/256, 256>>>(e0, e1, dv, dis, rowcur, colidx, wcsr);
    k_spmm_f<<<(N_POI+7)/8, 256>>>((const uint2*)tmpH, rowptr, colidx, wcsr, dis,
                                   (const float4*)(gcnb + 0*DIM),
                                   (uint2*)encH, (float4*)bA, 0);          // layer 1 SpMM+epi

    for (int i = 1; i < GCN_NUM; i++){
        k_gemm_p<<<(N_POI+127)/128, 256, smem_gemm>>>(
            (const uint2*)encH, (const uint2*)(WH + i*DIM*DIM), (uint32_t*)tmpH, N_POI);
        k_spmm_f<<<(N_POI+7)/8, 256>>>((const uint2*)tmpH, rowptr, colidx, wcsr, dis,
                                       (const float4*)(gcnb + i*DIM),
                                       (uint2*)encH, (float4*)bA,
                                       (i == GCN_NUM-1) ? 1 : 0);
    }
    const float* encF = bA;

    // attention
    k_qkv2<<<dim3(NTOK/128, 3), 256, smem_qkv>>>((const float4*)encF, xidx, inw, inb,
                                                 (float4*)qkv);
    k_attn<<<dim3(BATCH, 8), 128, smem_attn>>>(qkv, obuf);
    k_tail<<<BATCH, 128>>>(obuf, ow, ob, encF, pidx, out);
}

// round 13
// speedup vs baseline: 1.3891x; 1.0656x over previous
#include <cuda_runtime.h>
#include <cuda_fp16.h>
#include <math.h>
#include <stdint.h>

#define N_POI 50000
#define DIM 128
#define E_EDGES 400000
#define GCN_NUM 3
#define BATCH 64
#define LSEQ 100
#define NTOK (BATCH*LSEQ)
#define DIRE (2*E_EDGES)

// ---------------- device scratch ----------------
__device__ __align__(16) int    g_cnt[N_POI];
__device__ __align__(16) int    g_rowptr[N_POI+1];
__device__ __align__(16) int    g_rowcur[N_POI];
__device__ __align__(16) float  g_dis[N_POI];
__device__ __align__(16) int    g_colidx[DIRE];
__device__ __align__(16) float  g_wcsr[DIRE];
__device__ __align__(16) float  g_bufA[N_POI*DIM];
__device__ __align__(16) __half g_tmpH[N_POI*DIM];
__device__ __align__(16) __half g_encH[N_POI*DIM];
__device__ __align__(16) __half g_WH[GCN_NUM*DIM*DIM];
__device__ __align__(16) float  g_qkv[NTOK*3*DIM];
__device__ __align__(16) float  g_o[NTOK*DIM];

// fp16 HMMA m16n8k16, fp32 accumulate
__device__ __forceinline__ void mma_f16(float* d, const uint32_t* a, const uint32_t* b){
    asm volatile("mma.sync.aligned.m16n8k16.row.col.f32.f16.f16.f32 "
        "{%0,%1,%2,%3}, {%4,%5,%6,%7}, {%8,%9}, {%0,%1,%2,%3};"
        : "+f"(d[0]), "+f"(d[1]), "+f"(d[2]), "+f"(d[3])
        : "r"(a[0]), "r"(a[1]), "r"(a[2]), "r"(a[3]), "r"(b[0]), "r"(b[1]));
}

// ---------------- #1: hist + fp16 converts ----------------
__global__ void k_hist_cvt(const int* __restrict__ e0, const int* __restrict__ e1,
                           int* cnt, const float4* __restrict__ emb4,
                           const float4* __restrict__ w4,
                           __half2* __restrict__ encH2, __half2* __restrict__ WH2){
    int i = blockIdx.x*256 + threadIdx.x;
    if (i < E_EDGES){
        atomicAdd(&cnt[e0[i]], 1);
        atomicAdd(&cnt[e1[i]], 1);
    }
    const int NE4 = N_POI*32;
    const int NW4 = GCN_NUM*DIM*32;
    for (int j = i; j < NE4 + NW4; j += gridDim.x*256){
        if (j < NE4){
            float4 v = emb4[j];
            encH2[j*2]     = __floats2half2_rn(v.x, v.y);
            encH2[j*2 + 1] = __floats2half2_rn(v.z, v.w);
        } else {
            int k = j - NE4;
            float4 v = w4[k];
            WH2[k*2]     = __floats2half2_rn(v.x, v.y);
            WH2[k*2 + 1] = __floats2half2_rn(v.z, v.w);
        }
    }
}
// ---------------- #2: scan ----------------
__global__ void k_scan(const int* __restrict__ cnt, int* __restrict__ rowptr,
                       int* __restrict__ rowcur, float* __restrict__ dis){
    __shared__ int sh[1024];
    int t = threadIdx.x;
    const int CH = (N_POI + 1023)/1024;
    int base = t*CH;
    int s = 0;
    for (int i = 0; i < CH; i++){
        int idx = base + i;
        if (idx < N_POI) s += cnt[idx];
    }
    sh[t] = s;
    __syncthreads();
    for (int o = 1; o < 1024; o <<= 1){
        int v = (t >= o) ? sh[t-o] : 0;
        __syncthreads();
        sh[t] += v;
        __syncthreads();
    }
    int off = (t == 0) ? 0 : sh[t-1];
    for (int i = 0; i < CH; i++){
        int idx = base + i;
        if (idx < N_POI){
            int c = cnt[idx];
            rowptr[idx] = off;
            rowcur[idx] = off;
            dis[idx] = rsqrtf((float)(c + 1));
            off += c;
        }
    }
    if (t == 1023) rowptr[N_POI] = sh[1023];
}
// ---------------- #3: scatter ----------------
__global__ void k_scatter(const int* __restrict__ e0, const int* __restrict__ e1,
                          const float* __restrict__ dv, const float* __restrict__ dis,
                          int* rowcur, int* __restrict__ colidx, float* __restrict__ wcsr){
    int e = blockIdx.x*256 + threadIdx.x;
    if (e >= E_EDGES) return;
    int a = e0[e], b = e1[e];
    float d = dv[e];
    float wv = expf(-d*d) * dis[a] * dis[b];
    int p = atomicAdd(&rowcur[a], 1);
    colidx[p] = b; wcsr[p] = wv;
    p = atomicAdd(&rowcur[b], 1);
    colidx[p] = a; wcsr[p] = wv;
}

// ---------------- #4 (ncu slot): fp16 HMMA GEMM, 512 thr, 32x32 warp tile ----------------
#define PH 136
__global__ void __launch_bounds__(512, 2)
k_gemm_p(const uint2* __restrict__ Xh2, const uint2* __restrict__ WH2,
         uint32_t* __restrict__ tmpH, int M){
    extern __shared__ __half shh[];
    __half* As = shh;            // [128][PH]
    __half* Bs = shh + 128*PH;
    int tid = threadIdx.x;
    int row0 = blockIdx.x * 128;

    #pragma unroll
    for (int it = 0; it < 8; it++){
        int i = tid + it*512;
        int r = i >> 5, c8 = i & 31;
        int grow = row0 + r;
        uint2 av = (grow < M) ? Xh2[grow*32 + c8] : make_uint2(0u, 0u);
        *(uint2*)&As[r*PH + c8*4] = av;
        *(uint2*)&Bs[r*PH + c8*4] = WH2[i];
    }
    __syncthreads();

    int wid = tid >> 5, lane = tid & 31;
    int m_base = (wid & 3)*32, n_base = (wid >> 2)*32;
    int qr = lane >> 2, qc = lane & 3;

    float acc[2][4][4];
    #pragma unroll
    for (int mi = 0; mi < 2; mi++)
        #pragma unroll
        for (int ni = 0; ni < 4; ni++)
            #pragma unroll
            for (int j = 0; j < 4; j++) acc[mi][ni][j] = 0.f;

    #pragma unroll
    for (int k0 = 0; k0 < 128; k0 += 16){
        uint32_t a[2][4];
        #pragma unroll
        for (int mi = 0; mi < 2; mi++){
            const __half* ap = As + (m_base + mi*16 + qr)*PH + k0 + 2*qc;
            a[mi][0] = *(const uint32_t*)ap;
            a[mi][1] = *(const uint32_t*)(ap + 8*PH);
            a[mi][2] = *(const uint32_t*)(ap + 8);
            a[mi][3] = *(const uint32_t*)(ap + 8*PH + 8);
        }
        uint32_t b[4][2];
        #pragma unroll
        for (int ni = 0; ni < 4; ni++){
            const __half* bp = Bs + (n_base + ni*8 + qr)*PH + k0 + 2*qc;
            b[ni][0] = *(const uint32_t*)bp;
            b[ni][1] = *(const uint32_t*)(bp + 8);
        }
        #pragma unroll
        for (int mi = 0; mi < 2; mi++)
            #pragma unroll
            for (int ni = 0; ni < 4; ni++)
                mma_f16(acc[mi][ni], a[mi], b[ni]);
    }

    #pragma unroll
    for (int mi = 0; mi < 2; mi++){
        int r0 = row0 + m_base + mi*16 + qr;
        int r1 = r0 + 8;
        #pragma unroll
        for (int ni = 0; ni < 4; ni++){
            float* d = acc[mi][ni];
            int col = n_base + ni*8 + qc*2;
            if (r0 < M){
                __half2 h = __floats2half2_rn(d[0], d[1]);
                tmpH[r0*64 + (col >> 1)] = *(uint32_t*)&h;
            }
            if (r1 < M){
                __half2 h = __floats2half2_rn(d[2], d[3]);
                tmpH[r1*64 + (col >> 1)] = *(uint32_t*)&h;
            }
        }
    }
}

// ---------------- #5: SpMM on tmp + fused bias/lrelu/row-norm ----------------
__global__ void k_spmm_f(const uint2* __restrict__ tmpH2, const int* __restrict__ rowptr,
                         const int* __restrict__ cols, const float* __restrict__ ws,
                         const float* __restrict__ dis, const float4* __restrict__ bias4,
                         uint2* __restrict__ encH2, float4* __restrict__ outF4,
                         int writeF){
    int row = blockIdx.x*8 + (threadIdx.x >> 5);
    int lane = threadIdx.x & 31;
    if (row >= N_POI) return;
    float ds = dis[row];
    float sl = ds*ds;

    uint2 xs = tmpH2[row*32 + lane];
    float2 xa = __half22float2(*(const __half2*)&xs.x);
    float2 xb = __half22float2(*(const __half2*)&xs.y);
    float4 acc = make_float4(sl*xa.x, sl*xa.y, sl*xb.x, sl*xb.y);

    int s = __ldg(&rowptr[row]), e = __ldg(&rowptr[row+1]);
    int i = s;
    for (; i + 4 <= e; i += 4){
        int c0 = __ldg(&cols[i]),   c1 = __ldg(&cols[i+1]);
        int c2 = __ldg(&cols[i+2]), c3 = __ldg(&cols[i+3]);
        float w0 = __ldg(&ws[i]),   w1 = __ldg(&ws[i+1]);
        float w2 = __ldg(&ws[i+2]), w3 = __ldg(&ws[i+3]);
        uint2 u0 = tmpH2[c0*32 + lane];
        uint2 u1 = tmpH2[c1*32 + lane];
        uint2 u2 = tmpH2[c2*32 + lane];
        uint2 u3 = tmpH2[c3*32 + lane];
        float2 a0 = __half22float2(*(const __half2*)&u0.x), b0 = __half22float2(*(const __half2*)&u0.y);
        float2 a1 = __half22float2(*(const __half2*)&u1.x), b1 = __half22float2(*(const __half2*)&u1.y);
        float2 a2 = __half22float2(*(const __half2*)&u2.x), b2 = __half22float2(*(const __half2*)&u2.y);
        float2 a3 = __half22float2(*(const __half2*)&u3.x), b3 = __half22float2(*(const __half2*)&u3.y);
        acc.x = fmaf(w3,a3.x, fmaf(w2,a2.x, fmaf(w1,a1.x, fmaf(w0,a0.x, acc.x))));
        acc.y = fmaf(w3,a3.y, fmaf(w2,a2.y, fmaf(w1,a1.y, fmaf(w0,a0.y, acc.y))));
        acc.z = fmaf(w3,b3.x, fmaf(w2,b2.x, fmaf(w1,b1.x, fmaf(w0,b0.x, acc.z))));
        acc.w = fmaf(w3,b3.y, fmaf(w2,b2.y, fmaf(w1,b1.y, fmaf(w0,b0.y, acc.w))));
    }
    for (; i < e; i++){
        int c = __ldg(&cols[i]);
        float wv = __ldg(&ws[i]);
        uint2 u = tmpH2[c*32 + lane];
        float2 a = __half22float2(*(const __half2*)&u.x);
        float2 b = __half22float2(*(const __half2*)&u.y);
        acc.x = fmaf(wv, a.x, acc.x);
        acc.y = fmaf(wv, a.y, acc.y);
        acc.z = fmaf(wv, b.x, acc.z);
        acc.w = fmaf(wv, b.y, acc.w);
    }

    float4 b = bias4[lane];
    float v0 = acc.x + b.x, v1 = acc.y + b.y, v2 = acc.z + b.z, v3 = acc.w + b.w;
    v0 = (v0 >= 0.f) ? v0 : 0.01f*v0;
    v1 = (v1 >= 0.f) ? v1 : 0.01f*v1;
    v2 = (v2 >= 0.f) ? v2 : 0.01f*v2;
    v3 = (v3 >= 0.f) ? v3 : 0.01f*v3;
    float ss = fmaf(v0,v0, fmaf(v1,v1, fmaf(v2,v2, v3*v3)));
    #pragma unroll
    for (int o = 16; o > 0; o >>= 1) ss += __shfl_xor_sync(0xffffffffu, ss, o);
    float inv = 1.0f / fmaxf(sqrtf(ss), 1e-12f);
    float y0 = v0*inv, y1 = v1*inv, y2 = v2*inv, y3 = v3*inv;
    uint2 oh;
    *(__half2*)&oh.x = __floats2half2_rn(y0, y1);
    *(__half2*)&oh.y = __floats2half2_rn(y2, y3);
    encH2[row*32 + lane] = oh;
    if (writeF) outF4[row*32 + lane] = make_float4(y0, y1, y2, y3);
}

// ---------------- QKV: scalar tiled GEMM ----------------
__global__ void __launch_bounds__(256, 1)
k_qkv2(const float4* __restrict__ enc4, const int* __restrict__ xidx,
       const float* __restrict__ inw, const float* __restrict__ inb,
       float4* __restrict__ qkv4){
    extern __shared__ float4 sh4[];
    float4* Xs = sh4;
    float4* Ws = sh4 + 4096;
    int tid = threadIdx.x;
    int row0 = blockIdx.x * 128;
    int nb = blockIdx.y;
    #pragma unroll
    for (int it = 0; it < 16; it++){
        int idx = tid + it*256;
        int m = idx >> 5, k4 = idx & 31;
        int src = __ldg(&xidx[row0 + m]);
        Xs[idx] = enc4[src*32 + k4];
    }
    const float4* W4 = (const float4*)(inw + nb*DIM*DIM);
    #pragma unroll
    for (int it = 0; it < 16; it++){
        int idx = tid + it*256;
        int n = idx >> 5, k4 = idx & 31;
        Ws[n*32 + (k4 ^ (n >> 3))] = W4[idx];
    }
    __syncthreads();

    int tx = tid & 15, ty = tid >> 4;
    float acc[8][8];
    #pragma unroll
    for (int r = 0; r < 8; r++)
        #pragma unroll
        for (int c = 0; c < 8; c++) acc[r][c] = 0.f;

    const float4* Xp = Xs + (ty*8)*32;
    const float4* Wp = Ws + (tx*8)*32;
    #pragma unroll 2
    for (int k4 = 0; k4 < 32; k4++){
        float4 xv[8], wv[8];
        #pragma unroll
        for (int r = 0; r < 8; r++) xv[r] = Xp[r*32 + k4];
        int ksw = k4 ^ tx;
        #pragma unroll
        for (int c = 0; c < 8; c++) wv[c] = Wp[c*32 + ksw];
        #pragma unroll
        for (int r = 0; r < 8; r++)
            #pragma unroll
            for (int c = 0; c < 8; c++){
                acc[r][c] = fmaf(xv[r].x, wv[c].x, acc[r][c]);
                acc[r][c] = fmaf(xv[r].y, wv[c].y, acc[r][c]);
                acc[r][c] = fmaf(xv[r].z, wv[c].z, acc[r][c]);
                acc[r][c] = fmaf(xv[r].w, wv[c].w, acc[r][c]);
            }
    }

    float bj[8];
    #pragma unroll
    for (int c = 0; c < 8; c++) bj[c] = __ldg(&inb[nb*DIM + tx*8 + c]);
    #pragma unroll
    for (int r = 0; r < 8; r++){
        int t = row0 + ty*8 + r;
        qkv4[t*96 + nb*32 + tx*2]     = make_float4(acc[r][0]+bj[0], acc[r][1]+bj[1], acc[r][2]+bj[2], acc[r][3]+bj[3]);
        qkv4[t*96 + nb*32 + tx*2 + 1] = make_float4(acc[r][4]+bj[4], acc[r][5]+bj[5], acc[r][6]+bj[6], acc[r][7]+bj[7]);
    }
}

// ---------------- attention: conflict-free, one block per (b, h) ----------------
__global__ void k_attn(const float* __restrict__ qkv, float* __restrict__ o){
    extern __shared__ float sha[];
    float* sq  = sha;
    float* skT = sha + LSEQ*16;
    float* sv  = sha + 2*LSEQ*16;
    float* sp  = sha + 3*LSEQ*16;
    int b = blockIdx.x, h = blockIdx.y;
    int tid = threadIdx.x;
    for (int idx = tid; idx < LSEQ*16; idx += 128){
        int t = idx >> 4, d = idx & 15;
        int base = (b*LSEQ + t)*(3*DIM) + h*16 + d;
        sq[idx] = qkv[base];
        sv[idx] = qkv[base + 2*DIM];
    }
    for (int idx = tid; idx < LSEQ*16; idx += 128){
        int d = idx / LSEQ, t = idx - d*LSEQ;
        skT[idx] = qkv[(b*LSEQ + t)*(3*DIM) + DIM + h*16 + d];
    }
    __syncthreads();

    int lane = tid & 31, warp = tid >> 5;
    for (int qi = warp; qi < LSEQ; qi += 4){
        float q[16];
        #pragma unroll
        for (int d = 0; d < 16; d++) q[d] = sq[qi*16 + d];
        float v[4];
        float m = -1e30f;
        #pragma unroll
        for (int g = 0; g < 4; g++){
            int j = lane + g*32;
            float s = -1e30f;
            if (j < LSEQ){
                s = 0.f;
                #pragma unroll
                for (int d = 0; d < 16; d++) s = fmaf(q[d], skT[d*LSEQ + j], s);
                s *= 0.25f;
            }
            v[g] = s;
            m = fmaxf(m, s);
        }
        #pragma unroll
        for (int t = 16; t > 0; t >>= 1) m = fmaxf(m, __shfl_xor_sync(0xffffffffu, m, t));
        float ssum = 0.f;
        #pragma unroll
        for (int g = 0; g < 4; g++){
            int j = lane + g*32;
            float p = (j < LSEQ) ? __expf(v[g] - m) : 0.f;
            v[g] = p;
            ssum += p;
        }
        #pragma unroll
        for (int t = 16; t > 0; t >>= 1) ssum += __shfl_xor_sync(0xffffffffu, ssum, t);
        float inv = 1.0f / ssum;
        #pragma unroll
        for (int g = 0; g < 4; g++){
            int j = lane + g*32;
            if (j < LSEQ) sp[qi*LSEQ + j] = v[g]*inv;
        }
    }
    __syncthreads();

    const float4* sv4 = (const float4*)sv;
    for (int u = tid; u < LSEQ*4; u += 128){
        int qi = u >> 2, dg = u & 3;
        float4 acc = make_float4(0.f,0.f,0.f,0.f);
        const float* pp = sp + qi*LSEQ;
        #pragma unroll 4
        for (int j = 0; j < LSEQ; j++){
            float p = pp[j];
            float4 vv = sv4[j*4 + dg];
            acc.x = fmaf(p, vv.x, acc.x);
            acc.y = fmaf(p, vv.y, acc.y);
            acc.z = fmaf(p, vv.z, acc.z);
            acc.w = fmaf(p, vv.w, acc.w);
        }
        *(float4*)&o[(b*LSEQ + qi)*DIM + h*16 + dg*4] = acc;
    }
}

// ---------------- mean over L + out-projection + target gather ----------------
__global__ void k_tail(const float* __restrict__ o, const float* __restrict__ ow,
                       const float* __restrict__ ob, const float* __restrict__ enc,
                       const int* __restrict__ pidx, float* __restrict__ out){
    __shared__ float sx[DIM];
    int b = blockIdx.x, j = threadIdx.x;
    float s = 0.0f;
    for (int i = 0; i < LSEQ; i++) s += o[(b*LSEQ + i)*DIM + j];
    sx[j] = s * (1.0f/LSEQ);
    __syncthreads();
    float acc = ob[j];
    #pragma unroll 4
    for (int k = 0; k < DIM; k++) acc += sx[k]*ow[j*DIM + k];
    out[b*DIM + j] = acc;
    out[BATCH*DIM + b*DIM + j] = enc[pidx[b]*DIM + j];
}

// ---------------- host launch ----------------
extern "C" void kernel_launch(void* const* d_in, const int* in_sizes, int n_in,
                              void* d_out, int out_size){
    const float* embeds = (const float*)d_in[0];
    const float* gcnW   = (const float*)d_in[1];
    const float* gcnb   = (const float*)d_in[2];
    const float* inw    = (const float*)d_in[3];
    const float* inb    = (const float*)d_in[4];
    const float* ow     = (const float*)d_in[5];
    const float* ob     = (const float*)d_in[6];
    const float* dv     = (const float*)d_in[7];
    const int*   edges  = (const int*)d_in[8];
    const int*   xidx   = (const int*)d_in[9];
    const int*   pidx   = (const int*)d_in[10];
    const int* e0 = edges;
    const int* e1 = edges + E_EDGES;
    float* out = (float*)d_out;

    int *cnt, *rowptr, *rowcur, *colidx;
    float *dis, *wcsr, *bA, *qkv, *obuf;
    __half *encH, *tmpH, *WH;
    cudaGetSymbolAddress((void**)&cnt,    g_cnt);
    cudaGetSymbolAddress((void**)&rowptr, g_rowptr);
    cudaGetSymbolAddress((void**)&rowcur, g_rowcur);
    cudaGetSymbolAddress((void**)&dis,    g_dis);
    cudaGetSymbolAddress((void**)&colidx, g_colidx);
    cudaGetSymbolAddress((void**)&wcsr,   g_wcsr);
    cudaGetSymbolAddress((void**)&bA,     g_bufA);
    cudaGetSymbolAddress((void**)&tmpH,   g_tmpH);
    cudaGetSymbolAddress((void**)&encH,   g_encH);
    cudaGetSymbolAddress((void**)&WH,     g_WH);
    cudaGetSymbolAddress((void**)&qkv,    g_qkv);
    cudaGetSymbolAddress((void**)&obuf,   g_o);

    const int smem_qkv  = 2*4096*(int)sizeof(float4);      // 131072
    const int smem_gemm = 2*128*PH*(int)sizeof(__half);    // 69632
    const int smem_attn = (3*LSEQ*16 + LSEQ*LSEQ)*(int)sizeof(float);
    cudaFuncSetAttribute(k_gemm_p, cudaFuncAttributeMaxDynamicSharedMemorySize, smem_gemm);
    cudaFuncSetAttribute(k_qkv2,   cudaFuncAttributeMaxDynamicSharedMemorySize, smem_qkv);
    cudaFuncSetAttribute(k_attn,   cudaFuncAttributeMaxDynamicSharedMemorySize, smem_attn);

    // order: hist_cvt(1) scan(2) scatter(3) gemm1(4 <- ncu slot) spmm1(5) ...
    cudaMemsetAsync(cnt, 0, N_POI*sizeof(int));
    k_hist_cvt<<<6298, 256>>>(e0, e1, cnt, (const float4*)embeds, (const float4*)gcnW,
                              (__half2*)encH, (__half2*)WH);
    k_scan<<<1, 1024>>>(cnt, rowptr, rowcur, dis);
    k_scatter<<<(E_EDGES+255)/256, 256>>>(e0, e1, dv, dis, rowcur, colidx, wcsr);

    const __half* src = encH;
    for (int i = 0; i < GCN_NUM; i++){
        k_gemm_p<<<(N_POI+127)/128, 512, smem_gemm>>>(
            (const uint2*)src, (const uint2*)(WH + i*DIM*DIM), (uint32_t*)tmpH, N_POI);
        k_spmm_f<<<(N_POI+7)/8, 256>>>((const uint2*)tmpH, rowptr, colidx, wcsr, dis,
                                       (const float4*)(gcnb + i*DIM),
                                       (uint2*)encH, (float4*)bA,
                                       (i == GCN_NUM-1) ? 1 : 0);
        src = encH;
    }
    const float* encF = bA;

    // attention
    k_qkv2<<<dim3(NTOK/128, 3), 256, smem_qkv>>>((const float4*)encF, xidx, inw, inb,
                                                 (float4*)qkv);
    k_attn<<<dim3(BATCH, 8), 128, smem_attn>>>(qkv, obuf);
    k_tail<<<BATCH, 128>>>(obuf, ow, ob, encF, pidx, out);
}

// round 14
// speedup vs baseline: 1.9832x; 1.4277x over previous
#include <cuda_runtime.h>
#include <cuda_fp16.h>
#include <math.h>
#include <stdint.h>

#define N_POI 50000
#define DIM 128
#define E_EDGES 400000
#define GCN_NUM 3
#define BATCH 64
#define LSEQ 100
#define NTOK (BATCH*LSEQ)
#define DIRE (2*E_EDGES)
#define SCB 256
#define NSCB ((N_POI + SCB - 1)/SCB)   // 196

// ---------------- device scratch ----------------
__device__ __align__(16) int    g_cnt[N_POI];
__device__ __align__(16) int    g_part[NSCB];
__device__ __align__(16) int    g_rowptr[N_POI+1];
__device__ __align__(16) int    g_rowcur[N_POI];
__device__ __align__(16) float  g_dis[N_POI];
__device__ __align__(16) int    g_colidx[DIRE];
__device__ __align__(16) float  g_wcsr[DIRE];
__device__ __align__(16) float  g_bufA[N_POI*DIM];
__device__ __align__(16) __half g_tmpH[N_POI*DIM];
__device__ __align__(16) __half g_encH[N_POI*DIM];
__device__ __align__(16) __half g_WH[GCN_NUM*DIM*DIM];
__device__ __align__(16) float  g_qkv[NTOK*3*DIM];
__device__ __align__(16) float  g_o[NTOK*DIM];

// fp16 HMMA m16n8k16, fp32 accumulate
__device__ __forceinline__ void mma_f16(float* d, const uint32_t* a, const uint32_t* b){
    asm volatile("mma.sync.aligned.m16n8k16.row.col.f32.f16.f16.f32 "
        "{%0,%1,%2,%3}, {%4,%5,%6,%7}, {%8,%9}, {%0,%1,%2,%3};"
        : "+f"(d[0]), "+f"(d[1]), "+f"(d[2]), "+f"(d[3])
        : "r"(a[0]), "r"(a[1]), "r"(a[2]), "r"(a[3]), "r"(b[0]), "r"(b[1]));
}

// ---------------- #1: hist + fp16 converts ----------------
__global__ void k_hist_cvt(const int* __restrict__ e0, const int* __restrict__ e1,
                           int* cnt, const float4* __restrict__ emb4,
                           const float4* __restrict__ w4,
                           __half2* __restrict__ encH2, __half2* __restrict__ WH2){
    int i = blockIdx.x*256 + threadIdx.x;
    if (i < E_EDGES){
        atomicAdd(&cnt[e0[i]], 1);
        atomicAdd(&cnt[e1[i]], 1);
    }
    const int NE4 = N_POI*32;
    const int NW4 = GCN_NUM*DIM*32;
    for (int j = i; j < NE4 + NW4; j += gridDim.x*256){
        if (j < NE4){
            float4 v = emb4[j];
            encH2[j*2]     = __floats2half2_rn(v.x, v.y);
            encH2[j*2 + 1] = __floats2half2_rn(v.z, v.w);
        } else {
            int k = j - NE4;
            float4 v = w4[k];
            WH2[k*2]     = __floats2half2_rn(v.x, v.y);
            WH2[k*2 + 1] = __floats2half2_rn(v.z, v.w);
        }
    }
}

// ---------------- scanA: coalesced per-block sums ----------------
__global__ void k_scanA(const int* __restrict__ cnt, int* __restrict__ part){
    __shared__ int ws[8];
    int idx = blockIdx.x*SCB + threadIdx.x;
    int v = (idx < N_POI) ? cnt[idx] : 0;
    int s = v;
    #pragma unroll
    for (int o = 16; o > 0; o >>= 1) s += __shfl_xor_sync(0xffffffffu, s, o);
    int lane = threadIdx.x & 31, warp = threadIdx.x >> 5;
    if (lane == 0) ws[warp] = s;
    __syncthreads();
    if (threadIdx.x == 0){
        int t = 0;
        #pragma unroll
        for (int w = 0; w < 8; w++) t += ws[w];
        part[blockIdx.x] = t;
    }
}

// ---------------- scanB: global exclusive scan + coalesced outputs ----------------
__global__ void k_scanB(const int* __restrict__ cnt, const int* __restrict__ part,
                        int* __restrict__ rowptr, int* __restrict__ rowcur,
                        float* __restrict__ dis){
    __shared__ int sp[256];
    __shared__ int wsum[8];
    int t = threadIdx.x;
    int b = blockIdx.x;

    // scan the 196 block partials (redundant per block, cheap)
    sp[t] = (t < NSCB) ? part[t] : 0;
    __syncthreads();
    #pragma unroll
    for (int o = 1; o < 256; o <<= 1){
        int v = (t >= o) ? sp[t - o] : 0;
        __syncthreads();
        sp[t] += v;
        __syncthreads();
    }
    int base = (b == 0) ? 0 : sp[b - 1];
    int total = sp[NSCB - 1];

    // block-local exclusive scan of this chunk
    int idx = b*SCB + t;
    int v = (idx < N_POI) ? cnt[idx] : 0;
    int inc = v;
    int lane = t & 31, warp = t >> 5;
    #pragma unroll
    for (int o = 1; o < 32; o <<= 1){
        int x = __shfl_up_sync(0xffffffffu, inc, o);
        if (lane >= o) inc += x;
    }
    if (lane == 31) wsum[warp] = inc;
    __syncthreads();
    if (t < 8){
        int x = wsum[t];
        int acc = 0;
        #pragma unroll
        for (int w = 0; w < 8; w++){
            int y = (w < t) ? wsum[w] : 0;
            acc += y;
        }
        (void)x;
        wsum[t] = acc;   // exclusive warp offsets -- note: needs old values; recompute safely below
    }
    __syncthreads();
    // NOTE: the above in-place exclusive computation reads wsum[w<t] before any write
    // because each thread t<8 reads only indices < t, which are written by lower threads
    // in the same step; to be safe we recompute via a second smem array pattern:
    // (kept simple: wsum[t] now holds exclusive offset for warp t)
    int excl = inc - v + wsum[warp];
    if (idx < N_POI){
        int rp = base + excl;
        rowptr[idx] = rp;
        rowcur[idx] = rp;
        dis[idx] = rsqrtf((float)(v + 1));
    }
    if (b == 0 && t == 0) rowptr[N_POI] = total;
}

// ---------------- scatter ----------------
__global__ void k_scatter(const int* __restrict__ e0, const int* __restrict__ e1,
                          const float* __restrict__ dv, const float* __restrict__ dis,
                          int* rowcur, int* __restrict__ colidx, float* __restrict__ wcsr){
    int e = blockIdx.x*256 + threadIdx.x;
    if (e >= E_EDGES) return;
    int a = e0[e], b = e1[e];
    float d = dv[e];
    float wv = expf(-d*d) * dis[a] * dis[b];
    int p = atomicAdd(&rowcur[a], 1);
    colidx[p] = b; wcsr[p] = wv;
    p = atomicAdd(&rowcur[b], 1);
    colidx[p] = a; wcsr[p] = wv;
}

// ---------------- fp16 HMMA GEMM, 512 thr, 32x32 warp tile ----------------
#define PH 136
__global__ void __launch_bounds__(512, 2)
k_gemm_p(const uint2* __restrict__ Xh2, const uint2* __restrict__ WH2,
         uint32_t* __restrict__ tmpH, int M){
    extern __shared__ __half shh[];
    __half* As = shh;
    __half* Bs = shh + 128*PH;
    int tid = threadIdx.x;
    int row0 = blockIdx.x * 128;

    #pragma unroll
    for (int it = 0; it < 8; it++){
        int i = tid + it*512;
        int r = i >> 5, c8 = i & 31;
        int grow = row0 + r;
        uint2 av = (grow < M) ? Xh2[grow*32 + c8] : make_uint2(0u, 0u);
        *(uint2*)&As[r*PH + c8*4] = av;
        *(uint2*)&Bs[r*PH + c8*4] = WH2[i];
    }
    __syncthreads();

    int wid = tid >> 5, lane = tid & 31;
    int m_base = (wid & 3)*32, n_base = (wid >> 2)*32;
    int qr = lane >> 2, qc = lane & 3;

    float acc[2][4][4];
    #pragma unroll
    for (int mi = 0; mi < 2; mi++)
        #pragma unroll
        for (int ni = 0; ni < 4; ni++)
            #pragma unroll
            for (int j = 0; j < 4; j++) acc[mi][ni][j] = 0.f;

    #pragma unroll
    for (int k0 = 0; k0 < 128; k0 += 16){
        uint32_t a[2][4];
        #pragma unroll
        for (int mi = 0; mi < 2; mi++){
            const __half* ap = As + (m_base + mi*16 + qr)*PH + k0 + 2*qc;
            a[mi][0] = *(const uint32_t*)ap;
            a[mi][1] = *(const uint32_t*)(ap + 8*PH);
            a[mi][2] = *(const uint32_t*)(ap + 8);
            a[mi][3] = *(const uint32_t*)(ap + 8*PH + 8);
        }
        uint32_t b[4][2];
        #pragma unroll
        for (int ni = 0; ni < 4; ni++){
            const __half* bp = Bs + (n_base + ni*8 + qr)*PH + k0 + 2*qc;
            b[ni][0] = *(const uint32_t*)bp;
            b[ni][1] = *(const uint32_t*)(bp + 8);
        }
        #pragma unroll
        for (int mi = 0; mi < 2; mi++)
            #pragma unroll
            for (int ni = 0; ni < 4; ni++)
                mma_f16(acc[mi][ni], a[mi], b[ni]);
    }

    #pragma unroll
    for (int mi = 0; mi < 2; mi++){
        int r0 = row0 + m_base + mi*16 + qr;
        int r1 = r0 + 8;
        #pragma unroll
        for (int ni = 0; ni < 4; ni++){
            float* d = acc[mi][ni];
            int col = n_base + ni*8 + qc*2;
            if (r0 < M){
                __half2 h = __floats2half2_rn(d[0], d[1]);
                tmpH[r0*64 + (col >> 1)] = *(uint32_t*)&h;
            }
            if (r1 < M){
                __half2 h = __floats2half2_rn(d[2], d[3]);
                tmpH[r1*64 + (col >> 1)] = *(uint32_t*)&h;
            }
        }
    }
}

// ---------------- SpMM + fused bias/lrelu/row-norm ----------------
__global__ void k_spmm_f(const uint2* __restrict__ tmpH2, const int* __restrict__ rowptr,
                         const int* __restrict__ cols, const float* __restrict__ ws,
                         const float* __restrict__ dis, const float4* __restrict__ bias4,
                         uint2* __restrict__ encH2, float4* __restrict__ outF4,
                         int writeF){
    int row = blockIdx.x*8 + (threadIdx.x >> 5);
    int lane = threadIdx.x & 31;
    if (row >= N_POI) return;
    float ds = dis[row];
    float sl = ds*ds;

    uint2 xs = tmpH2[row*32 + lane];
    float2 xa = __half22float2(*(const __half2*)&xs.x);
    float2 xb = __half22float2(*(const __half2*)&xs.y);
    float4 acc = make_float4(sl*xa.x, sl*xa.y, sl*xb.x, sl*xb.y);

    int s = __ldg(&rowptr[row]), e = __ldg(&rowptr[row+1]);
    int i = s;
    for (; i + 4 <= e; i += 4){
        int c0 = __ldg(&cols[i]),   c1 = __ldg(&cols[i+1]);
        int c2 = __ldg(&cols[i+2]), c3 = __ldg(&cols[i+3]);
        float w0 = __ldg(&ws[i]),   w1 = __ldg(&ws[i+1]);
        float w2 = __ldg(&ws[i+2]), w3 = __ldg(&ws[i+3]);
        uint2 u0 = tmpH2[c0*32 + lane];
        uint2 u1 = tmpH2[c1*32 + lane];
        uint2 u2 = tmpH2[c2*32 + lane];
        uint2 u3 = tmpH2[c3*32 + lane];
        float2 a0 = __half22float2(*(const __half2*)&u0.x), b0 = __half22float2(*(const __half2*)&u0.y);
        float2 a1 = __half22float2(*(const __half2*)&u1.x), b1 = __half22float2(*(const __half2*)&u1.y);
        float2 a2 = __half22float2(*(const __half2*)&u2.x), b2 = __half22float2(*(const __half2*)&u2.y);
        float2 a3 = __half22float2(*(const __half2*)&u3.x), b3 = __half22float2(*(const __half2*)&u3.y);
        acc.x = fmaf(w3,a3.x, fmaf(w2,a2.x, fmaf(w1,a1.x, fmaf(w0,a0.x, acc.x))));
        acc.y = fmaf(w3,a3.y, fmaf(w2,a2.y, fmaf(w1,a1.y, fmaf(w0,a0.y, acc.y))));
        acc.z = fmaf(w3,b3.x, fmaf(w2,b2.x, fmaf(w1,b1.x, fmaf(w0,b0.x, acc.z))));
        acc.w = fmaf(w3,b3.y, fmaf(w2,b2.y, fmaf(w1,b1.y, fmaf(w0,b0.y, acc.w))));
    }
    for (; i < e; i++){
        int c = __ldg(&cols[i]);
        float wv = __ldg(&ws[i]);
        uint2 u = tmpH2[c*32 + lane];
        float2 a = __half22float2(*(const __half2*)&u.x);
        float2 b = __half22float2(*(const __half2*)&u.y);
        acc.x = fmaf(wv, a.x, acc.x);
        acc.y = fmaf(wv, a.y, acc.y);
        acc.z = fmaf(wv, b.x, acc.z);
        acc.w = fmaf(wv, b.y, acc.w);
    }

    float4 b = bias4[lane];
    float v0 = acc.x + b.x, v1 = acc.y + b.y, v2 = acc.z + b.z, v3 = acc.w + b.w;
    v0 = (v0 >= 0.f) ? v0 : 0.01f*v0;
    v1 = (v1 >= 0.f) ? v1 : 0.01f*v1;
    v2 = (v2 >= 0.f) ? v2 : 0.01f*v2;
    v3 = (v3 >= 0.f) ? v3 : 0.01f*v3;
    float ss = fmaf(v0,v0, fmaf(v1,v1, fmaf(v2,v2, v3*v3)));
    #pragma unroll
    for (int o = 16; o > 0; o >>= 1) ss += __shfl_xor_sync(0xffffffffu, ss, o);
    float inv = 1.0f / fmaxf(sqrtf(ss), 1e-12f);
    float y0 = v0*inv, y1 = v1*inv, y2 = v2*inv, y3 = v3*inv;
    uint2 oh;
    *(__half2*)&oh.x = __floats2half2_rn(y0, y1);
    *(__half2*)&oh.y = __floats2half2_rn(y2, y3);
    encH2[row*32 + lane] = oh;
    if (writeF) outF4[row*32 + lane] = make_float4(y0, y1, y2, y3);
}

// ---------------- QKV: scalar tiled GEMM ----------------
__global__ void __launch_bounds__(256, 1)
k_qkv2(const float4* __restrict__ enc4, const int* __restrict__ xidx,
       const float* __restrict__ inw, const float* __restrict__ inb,
       float4* __restrict__ qkv4){
    extern __shared__ float4 sh4[];
    float4* Xs = sh4;
    float4* Ws = sh4 + 4096;
    int tid = threadIdx.x;
    int row0 = blockIdx.x * 128;
    int nb = blockIdx.y;
    #pragma unroll
    for (int it = 0; it < 16; it++){
        int idx = tid + it*256;
        int m = idx >> 5, k4 = idx & 31;
        int src = __ldg(&xidx[row0 + m]);
        Xs[idx] = enc4[src*32 + k4];
    }
    const float4* W4 = (const float4*)(inw + nb*DIM*DIM);
    #pragma unroll
    for (int it = 0; it < 16; it++){
        int idx = tid + it*256;
        int n = idx >> 5, k4 = idx & 31;
        Ws[n*32 + (k4 ^ (n >> 3))] = W4[idx];
    }
    __syncthreads();

    int tx = tid & 15, ty = tid >> 4;
    float acc[8][8];
    #pragma unroll
    for (int r = 0; r < 8; r++)
        #pragma unroll
        for (int c = 0; c < 8; c++) acc[r][c] = 0.f;

    const float4* Xp = Xs + (ty*8)*32;
    const float4* Wp = Ws + (tx*8)*32;
    #pragma unroll 2
    for (int k4 = 0; k4 < 32; k4++){
        float4 xv[8], wv[8];
        #pragma unroll
        for (int r = 0; r < 8; r++) xv[r] = Xp[r*32 + k4];
        int ksw = k4 ^ tx;
        #pragma unroll
        for (int c = 0; c < 8; c++) wv[c] = Wp[c*32 + ksw];
        #pragma unroll
        for (int r = 0; r < 8; r++)
            #pragma unroll
            for (int c = 0; c < 8; c++){
                acc[r][c] = fmaf(xv[r].x, wv[c].x, acc[r][c]);
                acc[r][c] = fmaf(xv[r].y, wv[c].y, acc[r][c]);
                acc[r][c] = fmaf(xv[r].z, wv[c].z, acc[r][c]);
                acc[r][c] = fmaf(xv[r].w, wv[c].w, acc[r][c]);
            }
    }

    float bj[8];
    #pragma unroll
    for (int c = 0; c < 8; c++) bj[c] = __ldg(&inb[nb*DIM + tx*8 + c]);
    #pragma unroll
    for (int r = 0; r < 8; r++){
        int t = row0 + ty*8 + r;
        qkv4[t*96 + nb*32 + tx*2]     = make_float4(acc[r][0]+bj[0], acc[r][1]+bj[1], acc[r][2]+bj[2], acc[r][3]+bj[3]);
        qkv4[t*96 + nb*32 + tx*2 + 1] = make_float4(acc[r][4]+bj[4], acc[r][5]+bj[5], acc[r][6]+bj[6], acc[r][7]+bj[7]);
    }
}

// ---------------- attention ----------------
__global__ void k_attn(const float* __restrict__ qkv, float* __restrict__ o){
    extern __shared__ float sha[];
    float* sq  = sha;
    float* skT = sha + LSEQ*16;
    float* sv  = sha + 2*LSEQ*16;
    float* sp  = sha + 3*LSEQ*16;
    int b = blockIdx.x, h = blockIdx.y;
    int tid = threadIdx.x;
    for (int idx = tid; idx < LSEQ*16; idx += 128){
        int t = idx >> 4, d = idx & 15;
        int base = (b*LSEQ + t)*(3*DIM) + h*16 + d;
        sq[idx] = qkv[base];
        sv[idx] = qkv[base + 2*DIM];
    }
    for (int idx = tid; idx < LSEQ*16; idx += 128){
        int d = idx / LSEQ, t = idx - d*LSEQ;
        skT[idx] = qkv[(b*LSEQ + t)*(3*DIM) + DIM + h*16 + d];
    }
    __syncthreads();

    int lane = tid & 31, warp = tid >> 5;
    for (int qi = warp; qi < LSEQ; qi += 4){
        float q[16];
        #pragma unroll
        for (int d = 0; d < 16; d++) q[d] = sq[qi*16 + d];
        float v[4];
        float m = -1e30f;
        #pragma unroll
        for (int g = 0; g < 4; g++){
            int j = lane + g*32;
            float s = -1e30f;
            if (j < LSEQ){
                s = 0.f;
                #pragma unroll
                for (int d = 0; d < 16; d++) s = fmaf(q[d], skT[d*LSEQ + j], s);
                s *= 0.25f;
            }
            v[g] = s;
            m = fmaxf(m, s);
        }
        #pragma unroll
        for (int t = 16; t > 0; t >>= 1) m = fmaxf(m, __shfl_xor_sync(0xffffffffu, m, t));
        float ssum = 0.f;
        #pragma unroll
        for (int g = 0; g < 4; g++){
            int j = lane + g*32;
            float p = (j < LSEQ) ? __expf(v[g] - m) : 0.f;
            v[g] = p;
            ssum += p;
        }
        #pragma unroll
        for (int t = 16; t > 0; t >>= 1) ssum += __shfl_xor_sync(0xffffffffu, ssum, t);
        float inv = 1.0f / ssum;
        #pragma unroll
        for (int g = 0; g < 4; g++){
            int j = lane + g*32;
            if (j < LSEQ) sp[qi*LSEQ + j] = v[g]*inv;
        }
    }
    __syncthreads();

    const float4* sv4 = (const float4*)sv;
    for (int u = tid; u < LSEQ*4; u += 128){
        int qi = u >> 2, dg = u & 3;
        float4 acc = make_float4(0.f,0.f,0.f,0.f);
        const float* pp = sp + qi*LSEQ;
        #pragma unroll 4
        for (int j = 0; j < LSEQ; j++){
            float p = pp[j];
            float4 vv = sv4[j*4 + dg];
            acc.x = fmaf(p, vv.x, acc.x);
            acc.y = fmaf(p, vv.y, acc.y);
            acc.z = fmaf(p, vv.z, acc.z);
            acc.w = fmaf(p, vv.w, acc.w);
        }
        *(float4*)&o[(b*LSEQ + qi)*DIM + h*16 + dg*4] = acc;
    }
}

// ---------------- tail ----------------
__global__ void k_tail(const float* __restrict__ o, const float* __restrict__ ow,
                       const float* __restrict__ ob, const float* __restrict__ enc,
                       const int* __restrict__ pidx, float* __restrict__ out){
    __shared__ float sx[DIM];
    int b = blockIdx.x, j = threadIdx.x;
    float s = 0.0f;
    for (int i = 0; i < LSEQ; i++) s += o[(b*LSEQ + i)*DIM + j];
    sx[j] = s * (1.0f/LSEQ);
    __syncthreads();
    float acc = ob[j];
    #pragma unroll 4
    for (int k = 0; k < DIM; k++) acc += sx[k]*ow[j*DIM + k];
    out[b*DIM + j] = acc;
    out[BATCH*DIM + b*DIM + j] = enc[pidx[b]*DIM + j];
}

// ---------------- host launch ----------------
extern "C" void kernel_launch(void* const* d_in, const int* in_sizes, int n_in,
                              void* d_out, int out_size){
    const float* embeds = (const float*)d_in[0];
    const float* gcnW   = (const float*)d_in[1];
    const float* gcnb   = (const float*)d_in[2];
    const float* inw    = (const float*)d_in[3];
    const float* inb    = (const float*)d_in[4];
    const float* ow     = (const float*)d_in[5];
    const float* ob     = (const float*)d_in[6];
    const float* dv     = (const float*)d_in[7];
    const int*   edges  = (const int*)d_in[8];
    const int*   xidx   = (const int*)d_in[9];
    const int*   pidx   = (const int*)d_in[10];
    const int* e0 = edges;
    const int* e1 = edges + E_EDGES;
    float* out = (float*)d_out;

    int *cnt, *part, *rowptr, *rowcur, *colidx;
    float *dis, *wcsr, *bA, *qkv, *obuf;
    __half *encH, *tmpH, *WH;
    cudaGetSymbolAddress((void**)&cnt,    g_cnt);
    cudaGetSymbolAddress((void**)&part,   g_part);
    cudaGetSymbolAddress((void**)&rowptr, g_rowptr);
    cudaGetSymbolAddress((void**)&rowcur, g_rowcur);
    cudaGetSymbolAddress((void**)&dis,    g_dis);
    cudaGetSymbolAddress((void**)&colidx, g_colidx);
    cudaGetSymbolAddress((void**)&wcsr,   g_wcsr);
    cudaGetSymbolAddress((void**)&bA,     g_bufA);
    cudaGetSymbolAddress((void**)&tmpH,   g_tmpH);
    cudaGetSymbolAddress((void**)&encH,   g_encH);
    cudaGetSymbolAddress((void**)&WH,     g_WH);
    cudaGetSymbolAddress((void**)&qkv,    g_qkv);
    cudaGetSymbolAddress((void**)&obuf,   g_o);

    const int smem_qkv  = 2*4096*(int)sizeof(float4);
    const int smem_gemm = 2*128*PH*(int)sizeof(__half);
    const int smem_attn = (3*LSEQ*16 + LSEQ*LSEQ)*(int)sizeof(float);
    cudaFuncSetAttribute(k_gemm_p, cudaFuncAttributeMaxDynamicSharedMemorySize, smem_gemm);
    cudaFuncSetAttribute(k_qkv2,   cudaFuncAttributeMaxDynamicSharedMemorySize, smem_qkv);
    cudaFuncSetAttribute(k_attn,   cudaFuncAttributeMaxDynamicSharedMemorySize, smem_attn);

    // order: hist_cvt(1) gemm1(2, needs only cvt) scanA(3) scanB(4 <- ncu slot) scatter(5) spmm1(6) ...
    cudaMemsetAsync(cnt, 0, N_POI*sizeof(int));
    k_hist_cvt<<<6298, 256>>>(e0, e1, cnt, (const float4*)embeds, (const float4*)gcnW,
                              (__half2*)encH, (__half2*)WH);
    k_gemm_p<<<(N_POI+127)/128, 512, smem_gemm>>>(
        (const uint2*)encH, (const uint2*)WH, (uint32_t*)tmpH, N_POI);
    k_scanA<<<NSCB, SCB>>>(cnt, part);
    k_scanB<<<NSCB, SCB>>>(cnt, part, rowptr, rowcur, dis);
    k_scatter<<<(E_EDGES+255)/256, 256>>>(e0, e1, dv, dis, rowcur, colidx, wcsr);
    k_spmm_f<<<(N_POI+7)/8, 256>>>((const uint2*)tmpH, rowptr, colidx, wcsr, dis,
                                   (const float4*)(gcnb + 0*DIM),
                                   (uint2*)encH, (float4*)bA, 0);

    for (int i = 1; i < GCN_NUM; i++){
        k_gemm_p<<<(N_POI+127)/128, 512, smem_gemm>>>(
            (const uint2*)encH, (const uint2*)(WH + i*DIM*DIM), (uint32_t*)tmpH, N_POI);
        k_spmm_f<<<(N_POI+7)/8, 256>>>((const uint2*)tmpH, rowptr, colidx, wcsr, dis,
                                       (const float4*)(gcnb + i*DIM),
                                       (uint2*)encH, (float4*)bA,
                                       (i == GCN_NUM-1) ? 1 : 0);
    }
    const float* encF = bA;

    // attention
    k_qkv2<<<dim3(NTOK/128, 3), 256, smem_qkv>>>((const float4*)encF, xidx, inw, inb,
                                                 (float4*)qkv);
    k_attn<<<dim3(BATCH, 8), 128, smem_attn>>>(qkv, obuf);
    k_tail<<<BATCH, 128>>>(obuf, ow, ob, encF, pidx, out);
}

// round 15
// speedup vs baseline: 2.0174x; 1.0172x over previous
#include <cuda_runtime.h>
#include <cuda_fp16.h>
#include <math.h>
#include <stdint.h>

#define N_POI 50000
#define DIM 128
#define E_EDGES 400000
#define GCN_NUM 3
#define BATCH 64
#define LSEQ 100
#define NTOK (BATCH*LSEQ)
#define DIRE (2*E_EDGES)
#define SCB 256
#define NSCB ((N_POI + SCB - 1)/SCB)   // 196

// ---------------- device scratch ----------------
__device__ __align__(16) int    g_cnt[N_POI];
__device__ __align__(16) int    g_part[NSCB];
__device__ __align__(16) int    g_rowptr[N_POI+1];
__device__ __align__(16) int    g_rowcur[N_POI];
__device__ __align__(16) float  g_dis[N_POI];
__device__ __align__(16) int    g_colidx[DIRE+4];
__device__ __align__(16) float  g_wcsr[DIRE+4];
__device__ __align__(16) float  g_bufA[N_POI*DIM];
__device__ __align__(16) __half g_tmpH[N_POI*DIM];
__device__ __align__(16) __half g_encH[N_POI*DIM];
__device__ __align__(16) __half g_WH[GCN_NUM*DIM*DIM];
__device__ __align__(16) __half g_inwH[3*DIM*DIM];
__device__ __align__(16) float  g_qkv[NTOK*3*DIM];
__device__ __align__(16) float  g_o[NTOK*DIM];

// fp16 HMMA m16n8k16, fp32 accumulate
__device__ __forceinline__ void mma_f16(float* d, const uint32_t* a, const uint32_t* b){
    asm volatile("mma.sync.aligned.m16n8k16.row.col.f32.f16.f16.f32 "
        "{%0,%1,%2,%3}, {%4,%5,%6,%7}, {%8,%9}, {%0,%1,%2,%3};"
        : "+f"(d[0]), "+f"(d[1]), "+f"(d[2]), "+f"(d[3])
        : "r"(a[0]), "r"(a[1]), "r"(a[2]), "r"(a[3]), "r"(b[0]), "r"(b[1]));
}

// ---------------- #1: hist + fp16 converts (embeds, gcnW, inw) ----------------
__global__ void k_hist_cvt(const int* __restrict__ e0, const int* __restrict__ e1,
                           int* cnt, const float4* __restrict__ emb4,
                           const float4* __restrict__ w4, const float4* __restrict__ inw4,
                           __half2* __restrict__ encH2, __half2* __restrict__ WH2,
                           __half2* __restrict__ inwH2){
    int i = blockIdx.x*256 + threadIdx.x;
    if (i < E_EDGES){
        atomicAdd(&cnt[e0[i]], 1);
        atomicAdd(&cnt[e1[i]], 1);
    }
    const int NE4 = N_POI*32;
    const int NW4 = GCN_NUM*DIM*32;
    const int NI4 = 3*DIM*32;
    for (int j = i; j < NE4 + NW4 + NI4; j += gridDim.x*256){
        if (j < NE4){
            float4 v = emb4[j];
            encH2[j*2]     = __floats2half2_rn(v.x, v.y);
            encH2[j*2 + 1] = __floats2half2_rn(v.z, v.w);
        } else if (j < NE4 + NW4){
            int k = j - NE4;
            float4 v = w4[k];
            WH2[k*2]     = __floats2half2_rn(v.x, v.y);
            WH2[k*2 + 1] = __floats2half2_rn(v.z, v.w);
        } else {
            int k = j - NE4 - NW4;
            float4 v = inw4[k];
            inwH2[k*2]     = __floats2half2_rn(v.x, v.y);
            inwH2[k*2 + 1] = __floats2half2_rn(v.z, v.w);
        }
    }
}

// ---------------- scanA ----------------
__global__ void k_scanA(const int* __restrict__ cnt, int* __restrict__ part){
    __shared__ int ws[8];
    int idx = blockIdx.x*SCB + threadIdx.x;
    int v = (idx < N_POI) ? cnt[idx] : 0;
    int s = v;
    #pragma unroll
    for (int o = 16; o > 0; o >>= 1) s += __shfl_xor_sync(0xffffffffu, s, o);
    int lane = threadIdx.x & 31, warp = threadIdx.x >> 5;
    if (lane == 0) ws[warp] = s;
    __syncthreads();
    if (threadIdx.x == 0){
        int t = 0;
        #pragma unroll
        for (int w = 0; w < 8; w++) t += ws[w];
        part[blockIdx.x] = t;
    }
}

// ---------------- scanB ----------------
__global__ void k_scanB(const int* __restrict__ cnt, const int* __restrict__ part,
                        int* __restrict__ rowptr, int* __restrict__ rowcur,
                        float* __restrict__ dis){
    __shared__ int sp[256];
    __shared__ int wsum[8];
    int t = threadIdx.x;
    int b = blockIdx.x;

    sp[t] = (t < NSCB) ? part[t] : 0;
    __syncthreads();
    #pragma unroll
    for (int o = 1; o < 256; o <<= 1){
        int v = (t >= o) ? sp[t - o] : 0;
        __syncthreads();
        sp[t] += v;
        __syncthreads();
    }
    int base = (b == 0) ? 0 : sp[b - 1];
    int total = sp[NSCB - 1];

    int idx = b*SCB + t;
    int v = (idx < N_POI) ? cnt[idx] : 0;
    int inc = v;
    int lane = t & 31, warp = t >> 5;
    #pragma unroll
    for (int o = 1; o < 32; o <<= 1){
        int x = __shfl_up_sync(0xffffffffu, inc, o);
        if (lane >= o) inc += x;
    }
    if (lane == 31) wsum[warp] = inc;
    __syncthreads();
    if (t < 8){
        int acc = 0;
        #pragma unroll
        for (int w = 0; w < 8; w++){
            int y = (w < t) ? wsum[w] : 0;
            acc += y;
        }
        __syncwarp(0xffu);
        wsum[t] = acc;
    }
    __syncthreads();
    int excl = inc - v + wsum[warp];
    if (idx < N_POI){
        int rp = base + excl;
        rowptr[idx] = rp;
        rowcur[idx] = rp;
        dis[idx] = rsqrtf((float)(v + 1));
    }
    if (b == 0 && t == 0) rowptr[N_POI] = total;
}

// ---------------- scatter ----------------
__global__ void k_scatter(const int* __restrict__ e0, const int* __restrict__ e1,
                          const float* __restrict__ dv, const float* __restrict__ dis,
                          int* rowcur, int* __restrict__ colidx, float* __restrict__ wcsr){
    int e = blockIdx.x*256 + threadIdx.x;
    if (e >= E_EDGES) return;
    int a = e0[e], b = e1[e];
    float d = dv[e];
    float wv = expf(-d*d) * dis[a] * dis[b];
    int p = atomicAdd(&rowcur[a], 1);
    colidx[p] = b; wcsr[p] = wv;
    p = atomicAdd(&rowcur[b], 1);
    colidx[p] = a; wcsr[p] = wv;
}

// ---------------- fp16 HMMA GEMM, 512 thr, 32x32 warp tile ----------------
#define PH 136
__global__ void __launch_bounds__(512, 2)
k_gemm_p(const uint2* __restrict__ Xh2, const uint2* __restrict__ WH2,
         uint32_t* __restrict__ tmpH, int M){
    extern __shared__ __half shh[];
    __half* As = shh;
    __half* Bs = shh + 128*PH;
    int tid = threadIdx.x;
    int row0 = blockIdx.x * 128;

    #pragma unroll
    for (int it = 0; it < 8; it++){
        int i = tid + it*512;
        int r = i >> 5, c8 = i & 31;
        int grow = row0 + r;
        uint2 av = (grow < M) ? Xh2[grow*32 + c8] : make_uint2(0u, 0u);
        *(uint2*)&As[r*PH + c8*4] = av;
        *(uint2*)&Bs[r*PH + c8*4] = WH2[i];
    }
    __syncthreads();

    int wid = tid >> 5, lane = tid & 31;
    int m_base = (wid & 3)*32, n_base = (wid >> 2)*32;
    int qr = lane >> 2, qc = lane & 3;

    float acc[2][4][4];
    #pragma unroll
    for (int mi = 0; mi < 2; mi++)
        #pragma unroll
        for (int ni = 0; ni < 4; ni++)
            #pragma unroll
            for (int j = 0; j < 4; j++) acc[mi][ni][j] = 0.f;

    #pragma unroll
    for (int k0 = 0; k0 < 128; k0 += 16){
        uint32_t a[2][4];
        #pragma unroll
        for (int mi = 0; mi < 2; mi++){
            const __half* ap = As + (m_base + mi*16 + qr)*PH + k0 + 2*qc;
            a[mi][0] = *(const uint32_t*)ap;
            a[mi][1] = *(const uint32_t*)(ap + 8*PH);
            a[mi][2] = *(const uint32_t*)(ap + 8);
            a[mi][3] = *(const uint32_t*)(ap + 8*PH + 8);
        }
        uint32_t b[4][2];
        #pragma unroll
        for (int ni = 0; ni < 4; ni++){
            const __half* bp = Bs + (n_base + ni*8 + qr)*PH + k0 + 2*qc;
            b[ni][0] = *(const uint32_t*)bp;
            b[ni][1] = *(const uint32_t*)(bp + 8);
        }
        #pragma unroll
        for (int mi = 0; mi < 2; mi++)
            #pragma unroll
            for (int ni = 0; ni < 4; ni++)
                mma_f16(acc[mi][ni], a[mi], b[ni]);
    }

    #pragma unroll
    for (int mi = 0; mi < 2; mi++){
        int r0 = row0 + m_base + mi*16 + qr;
        int r1 = r0 + 8;
        #pragma unroll
        for (int ni = 0; ni < 4; ni++){
            float* d = acc[mi][ni];
            int col = n_base + ni*8 + qc*2;
            if (r0 < M){
                __half2 h = __floats2half2_rn(d[0], d[1]);
                tmpH[r0*64 + (col >> 1)] = *(uint32_t*)&h;
            }
            if (r1 < M){
                __half2 h = __floats2half2_rn(d[2], d[3]);
                tmpH[r1*64 + (col >> 1)] = *(uint32_t*)&h;
            }
        }
    }
}

// ---------------- SpMM paired-lane gather + fused epilogue ----------------
// lane half = edge parity within pair; sub = lane&15 covers 8 cols (uint4).
__global__ void k_spmm_f(const uint4* __restrict__ tmpH4, const int* __restrict__ rowptr,
                         const int* __restrict__ cols, const float* __restrict__ ws,
                         const float* __restrict__ dis, const float4* __restrict__ bias4,
                         uint4* __restrict__ encH4, float4* __restrict__ outF4,
                         int writeF){
    int row = blockIdx.x*8 + (threadIdx.x >> 5);
    int lane = threadIdx.x & 31;
    if (row >= N_POI) return;
    int half = lane >> 4, sub = lane & 15;
    float ds = dis[row];
    float sl = ds*ds;

    float acc[8];
    {
        uint4 x = tmpH4[row*16 + sub];
        float2 f0 = __half22float2(*(const __half2*)&x.x);
        float2 f1 = __half22float2(*(const __half2*)&x.y);
        float2 f2 = __half22float2(*(const __half2*)&x.z);
        float2 f3 = __half22float2(*(const __half2*)&x.w);
        float m = half ? 0.f : sl;
        acc[0]=m*f0.x; acc[1]=m*f0.y; acc[2]=m*f1.x; acc[3]=m*f1.y;
        acc[4]=m*f2.x; acc[5]=m*f2.y; acc[6]=m*f3.x; acc[7]=m*f3.y;
    }

    int s = __ldg(&rowptr[row]), e = __ldg(&rowptr[row+1]);
    for (int base = s; base < e; base += 4){
        int i0 = base + half, i1 = base + 2 + half;
        int ii0 = min(i0, e-1), ii1 = min(i1, e-1);
        float w0 = (i0 < e) ? __ldg(&ws[ii0]) : 0.f;
        float w1 = (i1 < e) ? __ldg(&ws[ii1]) : 0.f;
        int c0 = __ldg(&cols[ii0]);
        int c1 = __ldg(&cols[ii1]);
        uint4 g0 = tmpH4[c0*16 + sub];
        uint4 g1 = tmpH4[c1*16 + sub];
        float2 a0 = __half22float2(*(const __half2*)&g0.x), a1 = __half22float2(*(const __half2*)&g0.y);
        float2 a2 = __half22float2(*(const __half2*)&g0.z), a3 = __half22float2(*(const __half2*)&g0.w);
        float2 b0 = __half22float2(*(const __half2*)&g1.x), b1 = __half22float2(*(const __half2*)&g1.y);
        float2 b2 = __half22float2(*(const __half2*)&g1.z), b3 = __half22float2(*(const __half2*)&g1.w);
        acc[0] = fmaf(w1, b0.x, fmaf(w0, a0.x, acc[0]));
        acc[1] = fmaf(w1, b0.y, fmaf(w0, a0.y, acc[1]));
        acc[2] = fmaf(w1, b1.x, fmaf(w0, a1.x, acc[2]));
        acc[3] = fmaf(w1, b1.y, fmaf(w0, a1.y, acc[3]));
        acc[4] = fmaf(w1, b2.x, fmaf(w0, a2.x, acc[4]));
        acc[5] = fmaf(w1, b2.y, fmaf(w0, a2.y, acc[5]));
        acc[6] = fmaf(w1, b3.x, fmaf(w0, a3.x, acc[6]));
        acc[7] = fmaf(w1, b3.y, fmaf(w0, a3.y, acc[7]));
    }

    // combine lane halves
    #pragma unroll
    for (int i = 0; i < 8; i++) acc[i] += __shfl_xor_sync(0xffffffffu, acc[i], 16);

    // bias + lrelu + row L2 norm
    float4 bb0 = bias4[sub*2], bb1 = bias4[sub*2 + 1];
    float v[8];
    v[0] = acc[0] + bb0.x; v[1] = acc[1] + bb0.y; v[2] = acc[2] + bb0.z; v[3] = acc[3] + bb0.w;
    v[4] = acc[4] + bb1.x; v[5] = acc[5] + bb1.y; v[6] = acc[6] + bb1.z; v[7] = acc[7] + bb1.w;
    float ss = 0.f;
    #pragma unroll
    for (int i = 0; i < 8; i++){
        float t = v[i];
        t = (t >= 0.f) ? t : 0.01f*t;
        v[i] = t;
        ss = fmaf(t, t, ss);
    }
    #pragma unroll
    for (int o = 8; o > 0; o >>= 1) ss += __shfl_xor_sync(0xffffffffu, ss, o);
    float inv = 1.0f / fmaxf(sqrtf(ss), 1e-12f);
    #pragma unroll
    for (int i = 0; i < 8; i++) v[i] *= inv;

    if (half == 0){
        uint4 oh;
        *(__half2*)&oh.x = __floats2half2_rn(v[0], v[1]);
        *(__half2*)&oh.y = __floats2half2_rn(v[2], v[3]);
        *(__half2*)&oh.z = __floats2half2_rn(v[4], v[5]);
        *(__half2*)&oh.w = __floats2half2_rn(v[6], v[7]);
        encH4[row*16 + sub] = oh;
        if (writeF){
            outF4[row*32 + sub*2]     = make_float4(v[0], v[1], v[2], v[3]);
            outF4[row*32 + sub*2 + 1] = make_float4(v[4], v[5], v[6], v[7]);
        }
    }
}

// ---------------- QKV via fp16 HMMA (gathered rows), grid (50, 3) ----------------
__global__ void __launch_bounds__(512, 2)
k_qkv_h(const uint2* __restrict__ encH2, const int* __restrict__ xidx,
        const uint2* __restrict__ inwH2, const float* __restrict__ inb,
        float* __restrict__ qkv){
    extern __shared__ __half shh[];
    __half* As = shh;
    __half* Bs = shh + 128*PH;
    int tid = threadIdx.x;
    int row0 = blockIdx.x * 128;
    int nb = blockIdx.y;

    const uint2* W2 = inwH2 + nb*DIM*32;
    #pragma unroll
    for (int it = 0; it < 8; it++){
        int i = tid + it*512;
        int r = i >> 5, c8 = i & 31;
        int src = __ldg(&xidx[row0 + r]);
        *(uint2*)&As[r*PH + c8*4] = encH2[src*32 + c8];
        *(uint2*)&Bs[r*PH + c8*4] = W2[i];
    }
    __syncthreads();

    int wid = tid >> 5, lane = tid & 31;
    int m_base = (wid & 3)*32, n_base = (wid >> 2)*32;
    int qr = lane >> 2, qc = lane & 3;

    float acc[2][4][4];
    #pragma unroll
    for (int mi = 0; mi < 2; mi++)
        #pragma unroll
        for (int ni = 0; ni < 4; ni++)
            #pragma unroll
            for (int j = 0; j < 4; j++) acc[mi][ni][j] = 0.f;

    #pragma unroll
    for (int k0 = 0; k0 < 128; k0 += 16){
        uint32_t a[2][4];
        #pragma unroll
        for (int mi = 0; mi < 2; mi++){
            const __half* ap = As + (m_base + mi*16 + qr)*PH + k0 + 2*qc;
            a[mi][0] = *(const uint32_t*)ap;
            a[mi][1] = *(const uint32_t*)(ap + 8*PH);
            a[mi][2] = *(const uint32_t*)(ap + 8);
            a[mi][3] = *(const uint32_t*)(ap + 8*PH + 8);
        }
        uint32_t b[4][2];
        #pragma unroll
        for (int ni = 0; ni < 4; ni++){
            const __half* bp = Bs + (n_base + ni*8 + qr)*PH + k0 + 2*qc;
            b[ni][0] = *(const uint32_t*)bp;
            b[ni][1] = *(const uint32_t*)(bp + 8);
        }
        #pragma unroll
        for (int mi = 0; mi < 2; mi++)
            #pragma unroll
            for (int ni = 0; ni < 4; ni++)
                mma_f16(acc[mi][ni], a[mi], b[ni]);
    }

    #pragma unroll
    for (int mi = 0; mi < 2; mi++){
        int r0 = row0 + m_base + mi*16 + qr;
        int r1 = r0 + 8;
        #pragma unroll
        for (int ni = 0; ni < 4; ni++){
            float* d = acc[mi][ni];
            int col = n_base + ni*8 + qc*2;
            float2 bj = *(const float2*)&inb[nb*DIM + col];
            *(float2*)&qkv[r0*(3*DIM) + nb*DIM + col] = make_float2(d[0]+bj.x, d[1]+bj.y);
            *(float2*)&qkv[r1*(3*DIM) + nb*DIM + col] = make_float2(d[2]+bj.x, d[3]+bj.y);
        }
    }
}

// ---------------- attention ----------------
__global__ void k_attn(const float* __restrict__ qkv, float* __restrict__ o){
    extern __shared__ float sha[];
    float* sq  = sha;
    float* skT = sha + LSEQ*16;
    float* sv  = sha + 2*LSEQ*16;
    float* sp  = sha + 3*LSEQ*16;
    int b = blockIdx.x, h = blockIdx.y;
    int tid = threadIdx.x;
    for (int idx = tid; idx < LSEQ*16; idx += 128){
        int t = idx >> 4, d = idx & 15;
        int base = (b*LSEQ + t)*(3*DIM) + h*16 + d;
        sq[idx] = qkv[base];
        sv[idx] = qkv[base + 2*DIM];
    }
    for (int idx = tid; idx < LSEQ*16; idx += 128){
        int d = idx / LSEQ, t = idx - d*LSEQ;
        skT[idx] = qkv[(b*LSEQ + t)*(3*DIM) + DIM + h*16 + d];
    }
    __syncthreads();

    int lane = tid & 31, warp = tid >> 5;
    for (int qi = warp; qi < LSEQ; qi += 4){
        float q[16];
        #pragma unroll
        for (int d = 0; d < 16; d++) q[d] = sq[qi*16 + d];
        float v[4];
        float m = -1e30f;
        #pragma unroll
        for (int g = 0; g < 4; g++){
            int j = lane + g*32;
            float s = -1e30f;
            if (j < LSEQ){
                s = 0.f;
                #pragma unroll
                for (int d = 0; d < 16; d++) s = fmaf(q[d], skT[d*LSEQ + j], s);
                s *= 0.25f;
            }
            v[g] = s;
            m = fmaxf(m, s);
        }
        #pragma unroll
        for (int t = 16; t > 0; t >>= 1) m = fmaxf(m, __shfl_xor_sync(0xffffffffu, m, t));
        float ssum = 0.f;
        #pragma unroll
        for (int g = 0; g < 4; g++){
            int j = lane + g*32;
            float p = (j < LSEQ) ? __expf(v[g] - m) : 0.f;
            v[g] = p;
            ssum += p;
        }
        #pragma unroll
        for (int t = 16; t > 0; t >>= 1) ssum += __shfl_xor_sync(0xffffffffu, ssum, t);
        float inv = 1.0f / ssum;
        #pragma unroll
        for (int g = 0; g < 4; g++){
            int j = lane + g*32;
            if (j < LSEQ) sp[qi*LSEQ + j] = v[g]*inv;
        }
    }
    __syncthreads();

    const float4* sv4 = (const float4*)sv;
    for (int u = tid; u < LSEQ*4; u += 128){
        int qi = u >> 2, dg = u & 3;
        float4 acc = make_float4(0.f,0.f,0.f,0.f);
        const float* pp = sp + qi*LSEQ;
        #pragma unroll 4
        for (int j = 0; j < LSEQ; j++){
            float p = pp[j];
            float4 vv = sv4[j*4 + dg];
            acc.x = fmaf(p, vv.x, acc.x);
            acc.y = fmaf(p, vv.y, acc.y);
            acc.z = fmaf(p, vv.z, acc.z);
            acc.w = fmaf(p, vv.w, acc.w);
        }
        *(float4*)&o[(b*LSEQ + qi)*DIM + h*16 + dg*4] = acc;
    }
}

// ---------------- tail ----------------
__global__ void k_tail(const float* __restrict__ o, const float* __restrict__ ow,
                       const float* __restrict__ ob, const float* __restrict__ enc,
                       const int* __restrict__ pidx, float* __restrict__ out){
    __shared__ float sx[DIM];
    int b = blockIdx.x, j = threadIdx.x;
    float s = 0.0f;
    for (int i = 0; i < LSEQ; i++) s += o[(b*LSEQ + i)*DIM + j];
    sx[j] = s * (1.0f/LSEQ);
    __syncthreads();
    float acc = ob[j];
    #pragma unroll 4
    for (int k = 0; k < DIM; k++) acc += sx[k]*ow[j*DIM + k];
    out[b*DIM + j] = acc;
    out[BATCH*DIM + b*DIM + j] = enc[pidx[b]*DIM + j];
}

// ---------------- host launch ----------------
extern "C" void kernel_launch(void* const* d_in, const int* in_sizes, int n_in,
                              void* d_out, int out_size){
    const float* embeds = (const float*)d_in[0];
    const float* gcnW   = (const float*)d_in[1];
    const float* gcnb   = (const float*)d_in[2];
    const float* inw    = (const float*)d_in[3];
    const float* inb    = (const float*)d_in[4];
    const float* ow     = (const float*)d_in[5];
    const float* ob     = (const float*)d_in[6];
    const float* dv     = (const float*)d_in[7];
    const int*   edges  = (const int*)d_in[8];
    const int*   xidx   = (const int*)d_in[9];
    const int*   pidx   = (const int*)d_in[10];
    const int* e0 = edges;
    const int* e1 = edges + E_EDGES;
    float* out = (float*)d_out;

    int *cnt, *part, *rowptr, *rowcur, *colidx;
    float *dis, *wcsr, *bA, *qkv, *obuf;
    __half *encH, *tmpH, *WH, *inwH;
    cudaGetSymbolAddress((void**)&cnt,    g_cnt);
    cudaGetSymbolAddress((void**)&part,   g_part);
    cudaGetSymbolAddress((void**)&rowptr, g_rowptr);
    cudaGetSymbolAddress((void**)&rowcur, g_rowcur);
    cudaGetSymbolAddress((void**)&dis,    g_dis);
    cudaGetSymbolAddress((void**)&colidx, g_colidx);
    cudaGetSymbolAddress((void**)&wcsr,   g_wcsr);
    cudaGetSymbolAddress((void**)&bA,     g_bufA);
    cudaGetSymbolAddress((void**)&tmpH,   g_tmpH);
    cudaGetSymbolAddress((void**)&encH,   g_encH);
    cudaGetSymbolAddress((void**)&WH,     g_WH);
    cudaGetSymbolAddress((void**)&inwH,   g_inwH);
    cudaGetSymbolAddress((void**)&qkv,    g_qkv);
    cudaGetSymbolAddress((void**)&obuf,   g_o);

    const int smem_gemm = 2*128*PH*(int)sizeof(__half);
    const int smem_attn = (3*LSEQ*16 + LSEQ*LSEQ)*(int)sizeof(float);
    cudaFuncSetAttribute(k_gemm_p, cudaFuncAttributeMaxDynamicSharedMemorySize, smem_gemm);
    cudaFuncSetAttribute(k_qkv_h,  cudaFuncAttributeMaxDynamicSharedMemorySize, smem_gemm);
    cudaFuncSetAttribute(k_attn,   cudaFuncAttributeMaxDynamicSharedMemorySize, smem_attn);

    cudaMemsetAsync(cnt, 0, N_POI*sizeof(int));
    k_hist_cvt<<<6298, 256>>>(e0, e1, cnt, (const float4*)embeds, (const float4*)gcnW,
                              (const float4*)inw,
                              (__half2*)encH, (__half2*)WH, (__half2*)inwH);
    k_gemm_p<<<(N_POI+127)/128, 512, smem_gemm>>>(
        (const uint2*)encH, (const uint2*)WH, (uint32_t*)tmpH, N_POI);
    k_scanA<<<NSCB, SCB>>>(cnt, part);
    k_scanB<<<NSCB, SCB>>>(cnt, part, rowptr, rowcur, dis);
    k_scatter<<<(E_EDGES+255)/256, 256>>>(e0, e1, dv, dis, rowcur, colidx, wcsr);
    k_spmm_f<<<(N_POI+7)/8, 256>>>((const uint4*)tmpH, rowptr, colidx, wcsr, dis,
                                   (const float4*)(gcnb + 0*DIM),
                                   (uint4*)encH, (float4*)bA, 0);

    for (int i = 1; i < GCN_NUM; i++){
        k_gemm_p<<<(N_POI+127)/128, 512, smem_gemm>>>(
            (const uint2*)encH, (const uint2*)(WH + i*DIM*DIM), (uint32_t*)tmpH, N_POI);
        k_spmm_f<<<(N_POI+7)/8, 256>>>((const uint4*)tmpH, rowptr, colidx, wcsr, dis,
                                       (const float4*)(gcnb + i*DIM),
                                       (uint4*)encH, (float4*)bA,
                                       (i == GCN_NUM-1) ? 1 : 0);
    }
    const float* encF = bA;

    // attention
    k_qkv_h<<<dim3(NTOK/128, 3), 512, smem_gemm>>>((const uint2*)encH, xidx,
                                                   (const uint2*)inwH, inb, qkv);
    k_attn<<<dim3(BATCH, 8), 128, smem_attn>>>(qkv, obuf);
    k_tail<<<BATCH, 128>>>(obuf, ow, ob, encF, pidx, out);
}

// round 16
// speedup vs baseline: 2.1375x; 1.0595x over previous
#include <cuda_runtime.h>
#include <cuda_fp16.h>
#include <math.h>
#include <stdint.h>

#define N_POI 50000
#define DIM 128
#define E_EDGES 400000
#define GCN_NUM 3
#define BATCH 64
#define LSEQ 100
#define NTOK (BATCH*LSEQ)
#define DIRE (2*E_EDGES)
#define SCB 256
#define NSCB ((N_POI + SCB - 1)/SCB)   // 196

// ---------------- device scratch ----------------
__device__ __align__(16) int    g_cnt[N_POI];
__device__ __align__(16) int    g_part[NSCB];
__device__ __align__(16) int    g_rowptr[N_POI+1];
__device__ __align__(16) int    g_rowcur[N_POI];
__device__ __align__(16) float  g_dis[N_POI];
__device__ __align__(16) int    g_colidx[DIRE];
__device__ __align__(16) float  g_wcsr[DIRE];
__device__ __align__(16) float  g_bufA[N_POI*DIM];
__device__ __align__(16) __half g_tmpH[N_POI*DIM];
__device__ __align__(16) __half g_encH[N_POI*DIM];
__device__ __align__(16) float  g_qkv[NTOK*3*DIM];
__device__ __align__(16) float  g_o[NTOK*DIM];

// fp16 HMMA m16n8k16, fp32 accumulate
__device__ __forceinline__ void mma_f16(float* d, const uint32_t* a, const uint32_t* b){
    asm volatile("mma.sync.aligned.m16n8k16.row.col.f32.f16.f16.f32 "
        "{%0,%1,%2,%3}, {%4,%5,%6,%7}, {%8,%9}, {%0,%1,%2,%3};"
        : "+f"(d[0]), "+f"(d[1]), "+f"(d[2]), "+f"(d[3])
        : "r"(a[0]), "r"(a[1]), "r"(a[2]), "r"(a[3]), "r"(b[0]), "r"(b[1]));
}
__device__ __forceinline__ uint2 cvt_f4_h4(float4 v){
    uint2 h;
    *(__half2*)&h.x = __floats2half2_rn(v.x, v.y);
    *(__half2*)&h.y = __floats2half2_rn(v.z, v.w);
    return h;
}

// ---------------- #1: histogram only ----------------
__global__ void k_hist(const int* __restrict__ e0, const int* __restrict__ e1, int* cnt){
    int e = blockIdx.x*256 + threadIdx.x;
    if (e < E_EDGES){
        atomicAdd(&cnt[e0[e]], 1);
        atomicAdd(&cnt[e1[e]], 1);
    }
}

// ---------------- scanA ----------------
__global__ void k_scanA(const int* __restrict__ cnt, int* __restrict__ part){
    __shared__ int ws[8];
    int idx = blockIdx.x*SCB + threadIdx.x;
    int v = (idx < N_POI) ? cnt[idx] : 0;
    int s = v;
    #pragma unroll
    for (int o = 16; o > 0; o >>= 1) s += __shfl_xor_sync(0xffffffffu, s, o);
    int lane = threadIdx.x & 31, warp = threadIdx.x >> 5;
    if (lane == 0) ws[warp] = s;
    __syncthreads();
    if (threadIdx.x == 0){
        int t = 0;
        #pragma unroll
        for (int w = 0; w < 8; w++) t += ws[w];
        part[blockIdx.x] = t;
    }
}

// ---------------- scanB ----------------
__global__ void k_scanB(const int* __restrict__ cnt, const int* __restrict__ part,
                        int* __restrict__ rowptr, int* __restrict__ rowcur,
                        float* __restrict__ dis){
    __shared__ int sp[256];
    __shared__ int wsum[8];
    int t = threadIdx.x;
    int b = blockIdx.x;

    sp[t] = (t < NSCB) ? part[t] : 0;
    __syncthreads();
    #pragma unroll
    for (int o = 1; o < 256; o <<= 1){
        int v = (t >= o) ? sp[t - o] : 0;
        __syncthreads();
        sp[t] += v;
        __syncthreads();
    }
    int base = (b == 0) ? 0 : sp[b - 1];
    int total = sp[NSCB - 1];

    int idx = b*SCB + t;
    int v = (idx < N_POI) ? cnt[idx] : 0;
    int inc = v;
    int lane = t & 31, warp = t >> 5;
    #pragma unroll
    for (int o = 1; o < 32; o <<= 1){
        int x = __shfl_up_sync(0xffffffffu, inc, o);
        if (lane >= o) inc += x;
    }
    if (lane == 31) wsum[warp] = inc;
    __syncthreads();
    if (t < 8){
        int acc = 0;
        #pragma unroll
        for (int w = 0; w < 8; w++){
            int y = (w < t) ? wsum[w] : 0;
            acc += y;
        }
        __syncwarp(0xffu);
        wsum[t] = acc;
    }
    __syncthreads();
    int excl = inc - v + wsum[warp];
    if (idx < N_POI){
        int rp = base + excl;
        rowptr[idx] = rp;
        rowcur[idx] = rp;
        dis[idx] = rsqrtf((float)(v + 1));
    }
    if (b == 0 && t == 0) rowptr[N_POI] = total;
}

// ---------------- scatter ----------------
__global__ void k_scatter(const int* __restrict__ e0, const int* __restrict__ e1,
                          const float* __restrict__ dv, const float* __restrict__ dis,
                          int* rowcur, int* __restrict__ colidx, float* __restrict__ wcsr){
    int e = blockIdx.x*256 + threadIdx.x;
    if (e >= E_EDGES) return;
    int a = e0[e], b = e1[e];
    float d = dv[e];
    float wv = expf(-d*d) * dis[a] * dis[b];
    int p = atomicAdd(&rowcur[a], 1);
    colidx[p] = b; wcsr[p] = wv;
    p = atomicAdd(&rowcur[b], 1);
    colidx[p] = a; wcsr[p] = wv;
}

// ---------------- fp16 HMMA GEMM (A fp32 or fp16; W fp32, cvt in staging) ----------------
#define PH 136
__global__ void __launch_bounds__(512, 2)
k_gemm_p(const void* __restrict__ Xin, const float4* __restrict__ Wf4,
         uint32_t* __restrict__ tmpH, int M, int a_fp32){
    extern __shared__ __half shh[];
    __half* As = shh;
    __half* Bs = shh + 128*PH;
    int tid = threadIdx.x;
    int row0 = blockIdx.x * 128;

    if (a_fp32){
        const float4* X4 = (const float4*)Xin;
        #pragma unroll
        for (int it = 0; it < 8; it++){
            int i = tid + it*512;
            int r = i >> 5, c4 = i & 31;
            int grow = row0 + r;
            float4 v = (grow < M) ? X4[grow*32 + c4] : make_float4(0.f,0.f,0.f,0.f);
            *(uint2*)&As[r*PH + c4*4] = cvt_f4_h4(v);
            *(uint2*)&Bs[r*PH + c4*4] = cvt_f4_h4(Wf4[i]);
        }
    } else {
        const uint2* Xh2 = (const uint2*)Xin;
        #pragma unroll
        for (int it = 0; it < 8; it++){
            int i = tid + it*512;
            int r = i >> 5, c4 = i & 31;
            int grow = row0 + r;
            uint2 av = (grow < M) ? Xh2[grow*32 + c4] : make_uint2(0u, 0u);
            *(uint2*)&As[r*PH + c4*4] = av;
            *(uint2*)&Bs[r*PH + c4*4] = cvt_f4_h4(Wf4[i]);
        }
    }
    __syncthreads();

    int wid = tid >> 5, lane = tid & 31;
    int m_base = (wid & 3)*32, n_base = (wid >> 2)*32;
    int qr = lane >> 2, qc = lane & 3;

    float acc[2][4][4];
    #pragma unroll
    for (int mi = 0; mi < 2; mi++)
        #pragma unroll
        for (int ni = 0; ni < 4; ni++)
            #pragma unroll
            for (int j = 0; j < 4; j++) acc[mi][ni][j] = 0.f;

    #pragma unroll
    for (int k0 = 0; k0 < 128; k0 += 16){
        uint32_t a[2][4];
        #pragma unroll
        for (int mi = 0; mi < 2; mi++){
            const __half* ap = As + (m_base + mi*16 + qr)*PH + k0 + 2*qc;
            a[mi][0] = *(const uint32_t*)ap;
            a[mi][1] = *(const uint32_t*)(ap + 8*PH);
            a[mi][2] = *(const uint32_t*)(ap + 8);
            a[mi][3] = *(const uint32_t*)(ap + 8*PH + 8);
        }
        uint32_t b[4][2];
        #pragma unroll
        for (int ni = 0; ni < 4; ni++){
            const __half* bp = Bs + (n_base + ni*8 + qr)*PH + k0 + 2*qc;
            b[ni][0] = *(const uint32_t*)bp;
            b[ni][1] = *(const uint32_t*)(bp + 8);
        }
        #pragma unroll
        for (int mi = 0; mi < 2; mi++)
            #pragma unroll
            for (int ni = 0; ni < 4; ni++)
                mma_f16(acc[mi][ni], a[mi], b[ni]);
    }

    #pragma unroll
    for (int mi = 0; mi < 2; mi++){
        int r0 = row0 + m_base + mi*16 + qr;
        int r1 = r0 + 8;
        #pragma unroll
        for (int ni = 0; ni < 4; ni++){
            float* d = acc[mi][ni];
            int col = n_base + ni*8 + qc*2;
            if (r0 < M){
                __half2 h = __floats2half2_rn(d[0], d[1]);
                tmpH[r0*64 + (col >> 1)] = *(uint32_t*)&h;
            }
            if (r1 < M){
                __half2 h = __floats2half2_rn(d[2], d[3]);
                tmpH[r1*64 + (col >> 1)] = *(uint32_t*)&h;
            }
        }
    }
}

// ---------------- SpMM (R14-proven uint2 gather, 8-edge unroll) + fused epilogue ----------------
__global__ void k_spmm_f(const uint2* __restrict__ tmpH2, const int* __restrict__ rowptr,
                         const int* __restrict__ cols, const float* __restrict__ ws,
                         const float* __restrict__ dis, const float4* __restrict__ bias4,
                         uint2* __restrict__ encH2, float4* __restrict__ outF4,
                         int writeF){
    int row = blockIdx.x*8 + (threadIdx.x >> 5);
    int lane = threadIdx.x & 31;
    if (row >= N_POI) return;
    float ds = dis[row];
    float sl = ds*ds;

    uint2 xs = tmpH2[row*32 + lane];
    float2 xa = __half22float2(*(const __half2*)&xs.x);
    float2 xb = __half22float2(*(const __half2*)&xs.y);
    float4 acc = make_float4(sl*xa.x, sl*xa.y, sl*xb.x, sl*xb.y);

    int s = __ldg(&rowptr[row]), e = __ldg(&rowptr[row+1]);
    int i = s;
    for (; i + 8 <= e; i += 8){
        int c[8]; float w[8];
        #pragma unroll
        for (int j = 0; j < 8; j++){
            c[j] = __ldg(&cols[i + j]);
            w[j] = __ldg(&ws[i + j]);
        }
        #pragma unroll
        for (int j = 0; j < 8; j++){
            uint2 u = tmpH2[c[j]*32 + lane];
            float2 a = __half22float2(*(const __half2*)&u.x);
            float2 b = __half22float2(*(const __half2*)&u.y);
            acc.x = fmaf(w[j], a.x, acc.x);
            acc.y = fmaf(w[j], a.y, acc.y);
            acc.z = fmaf(w[j], b.x, acc.z);
            acc.w = fmaf(w[j], b.y, acc.w);
        }
    }
    for (; i < e; i++){
        int c = __ldg(&cols[i]);
        float wv = __ldg(&ws[i]);
        uint2 u = tmpH2[c*32 + lane];
        float2 a = __half22float2(*(const __half2*)&u.x);
        float2 b = __half22float2(*(const __half2*)&u.y);
        acc.x = fmaf(wv, a.x, acc.x);
        acc.y = fmaf(wv, a.y, acc.y);
        acc.z = fmaf(wv, b.x, acc.z);
        acc.w = fmaf(wv, b.y, acc.w);
    }

    float4 b = bias4[lane];
    float v0 = acc.x + b.x, v1 = acc.y + b.y, v2 = acc.z + b.z, v3 = acc.w + b.w;
    v0 = (v0 >= 0.f) ? v0 : 0.01f*v0;
    v1 = (v1 >= 0.f) ? v1 : 0.01f*v1;
    v2 = (v2 >= 0.f) ? v2 : 0.01f*v2;
    v3 = (v3 >= 0.f) ? v3 : 0.01f*v3;
    float ss = fmaf(v0,v0, fmaf(v1,v1, fmaf(v2,v2, v3*v3)));
    #pragma unroll
    for (int o = 16; o > 0; o >>= 1) ss += __shfl_xor_sync(0xffffffffu, ss, o);
    float inv = 1.0f / fmaxf(sqrtf(ss), 1e-12f);
    float y0 = v0*inv, y1 = v1*inv, y2 = v2*inv, y3 = v3*inv;
    uint2 oh;
    *(__half2*)&oh.x = __floats2half2_rn(y0, y1);
    *(__half2*)&oh.y = __floats2half2_rn(y2, y3);
    encH2[row*32 + lane] = oh;
    if (writeF) outF4[row*32 + lane] = make_float4(y0, y1, y2, y3);
}

// ---------------- QKV via fp16 HMMA (gathered rows; W fp32 cvt in staging) ----------------
__global__ void __launch_bounds__(512, 2)
k_qkv_h(const uint2* __restrict__ encH2, const int* __restrict__ xidx,
        const float4* __restrict__ inw4, const float* __restrict__ inb,
        float* __restrict__ qkv){
    extern __shared__ __half shh[];
    __half* As = shh;
    __half* Bs = shh + 128*PH;
    int tid = threadIdx.x;
    int row0 = blockIdx.x * 128;
    int nb = blockIdx.y;

    const float4* W4 = inw4 + nb*DIM*32;
    #pragma unroll
    for (int it = 0; it < 8; it++){
        int i = tid + it*512;
        int r = i >> 5, c4 = i & 31;
        int src = __ldg(&xidx[row0 + r]);
        *(uint2*)&As[r*PH + c4*4] = encH2[src*32 + c4];
        *(uint2*)&Bs[r*PH + c4*4] = cvt_f4_h4(W4[i]);
    }
    __syncthreads();

    int wid = tid >> 5, lane = tid & 31;
    int m_base = (wid & 3)*32, n_base = (wid >> 2)*32;
    int qr = lane >> 2, qc = lane & 3;

    float acc[2][4][4];
    #pragma unroll
    for (int mi = 0; mi < 2; mi++)
        #pragma unroll
        for (int ni = 0; ni < 4; ni++)
            #pragma unroll
            for (int j = 0; j < 4; j++) acc[mi][ni][j] = 0.f;

    #pragma unroll
    for (int k0 = 0; k0 < 128; k0 += 16){
        uint32_t a[2][4];
        #pragma unroll
        for (int mi = 0; mi < 2; mi++){
            const __half* ap = As + (m_base + mi*16 + qr)*PH + k0 + 2*qc;
            a[mi][0] = *(const uint32_t*)ap;
            a[mi][1] = *(const uint32_t*)(ap + 8*PH);
            a[mi][2] = *(const uint32_t*)(ap + 8);
            a[mi][3] = *(const uint32_t*)(ap + 8*PH + 8);
        }
        uint32_t b[4][2];
        #pragma unroll
        for (int ni = 0; ni < 4; ni++){
            const __half* bp = Bs + (n_base + ni*8 + qr)*PH + k0 + 2*qc;
            b[ni][0] = *(const uint32_t*)bp;
            b[ni][1] = *(const uint32_t*)(bp + 8);
        }
        #pragma unroll
        for (int mi = 0; mi < 2; mi++)
            #pragma unroll
            for (int ni = 0; ni < 4; ni++)
                mma_f16(acc[mi][ni], a[mi], b[ni]);
    }

    #pragma unroll
    for (int mi = 0; mi < 2; mi++){
        int r0 = row0 + m_base + mi*16 + qr;
        int r1 = r0 + 8;
        #pragma unroll
        for (int ni = 0; ni < 4; ni++){
            float* d = acc[mi][ni];
            int col = n_base + ni*8 + qc*2;
            float2 bj = *(const float2*)&inb[nb*DIM + col];
            *(float2*)&qkv[r0*(3*DIM) + nb*DIM + col] = make_float2(d[0]+bj.x, d[1]+bj.y);
            *(float2*)&qkv[r1*(3*DIM) + nb*DIM + col] = make_float2(d[2]+bj.x, d[3]+bj.y);
        }
    }
}

// ---------------- attention ----------------
__global__ void k_attn(const float* __restrict__ qkv, float* __restrict__ o){
    extern __shared__ float sha[];
    float* sq  = sha;
    float* skT = sha + LSEQ*16;
    float* sv  = sha + 2*LSEQ*16;
    float* sp  = sha + 3*LSEQ*16;
    int b = blockIdx.x, h = blockIdx.y;
    int tid = threadIdx.x;
    for (int idx = tid; idx < LSEQ*16; idx += 128){
        int t = idx >> 4, d = idx & 15;
        int base = (b*LSEQ + t)*(3*DIM) + h*16 + d;
        sq[idx] = qkv[base];
        sv[idx] = qkv[base + 2*DIM];
    }
    for (int idx = tid; idx < LSEQ*16; idx += 128){
        int d = idx / LSEQ, t = idx - d*LSEQ;
        skT[idx] = qkv[(b*LSEQ + t)*(3*DIM) + DIM + h*16 + d];
    }
    __syncthreads();

    int lane = tid & 31, warp = tid >> 5;
    for (int qi = warp; qi < LSEQ; qi += 4){
        float q[16];
        #pragma unroll
        for (int d = 0; d < 16; d++) q[d] = sq[qi*16 + d];
        float v[4];
        float m = -1e30f;
        #pragma unroll
        for (int g = 0; g < 4; g++){
            int j = lane + g*32;
            float s = -1e30f;
            if (j < LSEQ){
                s = 0.f;
                #pragma unroll
                for (int d = 0; d < 16; d++) s = fmaf(q[d], skT[d*LSEQ + j], s);
                s *= 0.25f;
            }
            v[g] = s;
            m = fmaxf(m, s);
        }
        #pragma unroll
        for (int t = 16; t > 0; t >>= 1) m = fmaxf(m, __shfl_xor_sync(0xffffffffu, m, t));
        float ssum = 0.f;
        #pragma unroll
        for (int g = 0; g < 4; g++){
            int j = lane + g*32;
            float p = (j < LSEQ) ? __expf(v[g] - m) : 0.f;
            v[g] = p;
            ssum += p;
        }
        #pragma unroll
        for (int t = 16; t > 0; t >>= 1) ssum += __shfl_xor_sync(0xffffffffu, ssum, t);
        float inv = 1.0f / ssum;
        #pragma unroll
        for (int g = 0; g < 4; g++){
            int j = lane + g*32;
            if (j < LSEQ) sp[qi*LSEQ + j] = v[g]*inv;
        }
    }
    __syncthreads();

    const float4* sv4 = (const float4*)sv;
    for (int u = tid; u < LSEQ*4; u += 128){
        int qi = u >> 2, dg = u & 3;
        float4 acc = make_float4(0.f,0.f,0.f,0.f);
        const float* pp = sp + qi*LSEQ;
        #pragma unroll 4
        for (int j = 0; j < LSEQ; j++){
            float p = pp[j];
            float4 vv = sv4[j*4 + dg];
            acc.x = fmaf(p, vv.x, acc.x);
            acc.y = fmaf(p, vv.y, acc.y);
            acc.z = fmaf(p, vv.z, acc.z);
            acc.w = fmaf(p, vv.w, acc.w);
        }
        *(float4*)&o[(b*LSEQ + qi)*DIM + h*16 + dg*4] = acc;
    }
}

// ---------------- tail ----------------
__global__ void k_tail(const float* __restrict__ o, const float* __restrict__ ow,
                       const float* __restrict__ ob, const float* __restrict__ enc,
                       const int* __restrict__ pidx, float* __restrict__ out){
    __shared__ float sx[DIM];
    int b = blockIdx.x, j = threadIdx.x;
    float s = 0.0f;
    for (int i = 0; i < LSEQ; i++) s += o[(b*LSEQ + i)*DIM + j];
    sx[j] = s * (1.0f/LSEQ);
    __syncthreads();
    float acc = ob[j];
    #pragma unroll 4
    for (int k = 0; k < DIM; k++) acc += sx[k]*ow[j*DIM + k];
    out[b*DIM + j] = acc;
    out[BATCH*DIM + b*DIM + j] = enc[pidx[b]*DIM + j];
}

// ---------------- host launch ----------------
extern "C" void kernel_launch(void* const* d_in, const int* in_sizes, int n_in,
                              void* d_out, int out_size){
    const float* embeds = (const float*)d_in[0];
    const float* gcnW   = (const float*)d_in[1];
    const float* gcnb   = (const float*)d_in[2];
    const float* inw    = (const float*)d_in[3];
    const float* inb    = (const float*)d_in[4];
    const float* ow     = (const float*)d_in[5];
    const float* ob     = (const float*)d_in[6];
    const float* dv     = (const float*)d_in[7];
    const int*   edges  = (const int*)d_in[8];
    const int*   xidx   = (const int*)d_in[9];
    const int*   pidx   = (const int*)d_in[10];
    const int* e0 = edges;
    const int* e1 = edges + E_EDGES;
    float* out = (float*)d_out;

    int *cnt, *part, *rowptr, *rowcur, *colidx;
    float *dis, *wcsr, *bA, *qkv, *obuf;
    __half *encH, *tmpH;
    cudaGetSymbolAddress((void**)&cnt,    g_cnt);
    cudaGetSymbolAddress((void**)&part,   g_part);
    cudaGetSymbolAddress((void**)&rowptr, g_rowptr);
    cudaGetSymbolAddress((void**)&rowcur, g_rowcur);
    cudaGetSymbolAddress((void**)&dis,    g_dis);
    cudaGetSymbolAddress((void**)&colidx, g_colidx);
    cudaGetSymbolAddress((void**)&wcsr,   g_wcsr);
    cudaGetSymbolAddress((void**)&bA,     g_bufA);
    cudaGetSymbolAddress((void**)&tmpH,   g_tmpH);
    cudaGetSymbolAddress((void**)&encH,   g_encH);
    cudaGetSymbolAddress((void**)&qkv,    g_qkv);
    cudaGetSymbolAddress((void**)&obuf,   g_o);

    const int smem_gemm = 2*128*PH*(int)sizeof(__half);
    const int smem_attn = (3*LSEQ*16 + LSEQ*LSEQ)*(int)sizeof(float);
    cudaFuncSetAttribute(k_gemm_p, cudaFuncAttributeMaxDynamicSharedMemorySize, smem_gemm);
    cudaFuncSetAttribute(k_qkv_h,  cudaFuncAttributeMaxDynamicSharedMemorySize, smem_gemm);
    cudaFuncSetAttribute(k_attn,   cudaFuncAttributeMaxDynamicSharedMemorySize, smem_attn);

    cudaMemsetAsync(cnt, 0, N_POI*sizeof(int));
    k_hist<<<(E_EDGES+255)/256, 256>>>(e0, e1, cnt);
    // layer-1 GEMM straight from fp32 embeds (independent of CSR build)
    k_gemm_p<<<(N_POI+127)/128, 512, smem_gemm>>>(
        (const void*)embeds, (const float4*)gcnW, (uint32_t*)tmpH, N_POI, 1);
    k_scanA<<<NSCB, SCB>>>(cnt, part);
    k_scanB<<<NSCB, SCB>>>(cnt, part, rowptr, rowcur, dis);
    k_scatter<<<(E_EDGES+255)/256, 256>>>(e0, e1, dv, dis, rowcur, colidx, wcsr);
    k_spmm_f<<<(N_POI+7)/8, 256>>>((const uint2*)tmpH, rowptr, colidx, wcsr, dis,
                                   (const float4*)(gcnb + 0*DIM),
                                   (uint2*)encH, (float4*)bA, 0);

    for (int i = 1; i < GCN_NUM; i++){
        k_gemm_p<<<(N_POI+127)/128, 512, smem_gemm>>>(
            (const void*)encH, (const float4*)(gcnW + i*DIM*DIM), (uint32_t*)tmpH,
            N_POI, 0);
        k_spmm_f<<<(N_POI+7)/8, 256>>>((const uint2*)tmpH, rowptr, colidx, wcsr, dis,
                                       (const float4*)(gcnb + i*DIM),
                                       (uint2*)encH, (float4*)bA,
                                       (i == GCN_NUM-1) ? 1 : 0);
    }
    const float* encF = bA;

    // attention
    k_qkv_h<<<dim3(NTOK/128, 3), 512, smem_gemm>>>((const uint2*)encH, xidx,
                                                   (const float4*)inw, inb, qkv);
    k_attn<<<dim3(BATCH, 8), 128, smem_attn>>>(qkv, obuf);
    k_tail<<<BATCH, 128>>>(obuf, ow, ob, encF, pidx, out);
}